// round 8
// baseline (speedup 1.0000x reference)
#include <cuda_runtime.h>
#include <cuda_bf16.h>
#include <math.h>
#include <stdint.h>

#define S_LEN   2048
#define HID_DIM 3584
#define NH      16
#define NKV     8
#define HD      256
#define QKV_N   ((NH + 2 * NKV) * HD)   // 8192
#define ATTN_N  (NH * HD)               // 4096
#define WIN     1024
#define SOFTCAP 50.0f
#define SCALING 0.0625f

// ---------------- scratch (__device__ globals; no allocs allowed) ----------
__device__ __align__(256) float g_qkv[S_LEN * QKV_N];    // 64 MB
__device__ __align__(256) float g_attn[S_LEN * ATTN_N];  // 32 MB
__device__ __align__(256) int8_t g_iA0[S_LEN * 4096];
__device__ __align__(256) int8_t g_iA1[S_LEN * 4096];
__device__ __align__(256) int8_t g_iB0[8192 * 4096];
__device__ __align__(256) int8_t g_iB1[8192 * 4096];
__device__ float g_sA[S_LEN];
__device__ float g_cmax[8192];
// per-head bf16 planes for attention
__device__ __align__(256) __nv_bfloat16 g_Qh[NH  * S_LEN * HD];
__device__ __align__(256) __nv_bfloat16 g_Ql[NH  * S_LEN * HD];
__device__ __align__(256) __nv_bfloat16 g_Kh[NKV * S_LEN * HD];
__device__ __align__(256) __nv_bfloat16 g_Kl[NKV * S_LEN * HD];
__device__ __align__(256) __nv_bfloat16 g_Vh[NKV * S_LEN * HD];
__device__ __align__(256) __nv_bfloat16 g_Vl[NKV * S_LEN * HD];

// ---------------- PTX helpers ----------------------------------------------
__device__ __forceinline__ uint32_t smem_u32(const void* p) {
    uint32_t a;
    asm("{ .reg .u64 t; cvta.to.shared.u64 t, %1; cvt.u32.u64 %0, t; }" : "=r"(a) : "l"(p));
    return a;
}
#define CP_ASYNC16(dst, src) \
    asm volatile("cp.async.cg.shared.global [%0], [%1], 16;" :: "r"(dst), "l"(src) : "memory")
#define CP_COMMIT() asm volatile("cp.async.commit_group;" ::: "memory")
#define CP_WAIT1()  asm volatile("cp.async.wait_group 1;" ::: "memory")

#define LDSM_X4(r0, r1, r2, r3, addr) \
    asm volatile("ldmatrix.sync.aligned.m8n8.x4.shared.b16 {%0,%1,%2,%3}, [%4];" \
        : "=r"(r0), "=r"(r1), "=r"(r2), "=r"(r3) : "r"(addr))
#define LDSM_X4T(r0, r1, r2, r3, addr) \
    asm volatile("ldmatrix.sync.aligned.m8n8.x4.trans.shared.b16 {%0,%1,%2,%3}, [%4];" \
        : "=r"(r0), "=r"(r1), "=r"(r2), "=r"(r3) : "r"(addr))

#define MMA_BF16(d, a, b0, b1) \
    asm volatile("mma.sync.aligned.m16n8k16.row.col.f32.bf16.bf16.f32 " \
        "{%0,%1,%2,%3}, {%4,%5,%6,%7}, {%8,%9}, {%0,%1,%2,%3};" \
        : "+f"((d)[0]), "+f"((d)[1]), "+f"((d)[2]), "+f"((d)[3]) \
        : "r"((a)[0]), "r"((a)[1]), "r"((a)[2]), "r"((a)[3]), "r"(b0), "r"(b1))

#define MMA_S8(d, a, b0_, b1_) \
    asm volatile("mma.sync.aligned.m16n8k32.row.col.s32.s8.s8.s32 " \
        "{%0,%1,%2,%3}, {%4,%5,%6,%7}, {%8,%9}, {%0,%1,%2,%3};" \
        : "+r"((d)[0]), "+r"((d)[1]), "+r"((d)[2]), "+r"((d)[3]) \
        : "r"((a)[0]), "r"((a)[1]), "r"((a)[2]), "r"((a)[3]), "r"(b0_), "r"(b1_))

__device__ __forceinline__ void split_bf16(float x, __nv_bfloat16& h, __nv_bfloat16& l) {
    h = __float2bfloat16_rn(x);
    l = __float2bfloat16_rn(x - __bfloat162float(h));
}
__device__ __forceinline__ void split2(float a, float b, uint32_t& hi, uint32_t& lo) {
    __nv_bfloat16 ha, la, hb, lb;
    split_bf16(a, ha, la); split_bf16(b, hb, lb);
    __nv_bfloat162 H; H.x = ha; H.y = hb;
    __nv_bfloat162 L; L.x = la; L.y = lb;
    hi = *reinterpret_cast<uint32_t*>(&H);
    lo = *reinterpret_cast<uint32_t*>(&L);
}

// ---------------------------------------------------------------------------
// quant_rows: per-row 2-term int8 quantization of fp32 [rows, K].
// ---------------------------------------------------------------------------
__global__ void quant_rows(const float* __restrict__ X, int K,
                           int8_t* __restrict__ A0, int8_t* __restrict__ A1,
                           float* __restrict__ sA)
{
    const int row = blockIdx.x, tid = threadIdx.x;
    const float* base = X + (size_t)row * K;
    float v[16];
    float mx = 0.f;
    int cnt = 0;
    for (int k = tid; k < K; k += 256) { v[cnt] = base[k]; mx = fmaxf(mx, fabsf(v[cnt])); cnt++; }
    __shared__ float red[256];
    red[tid] = mx; __syncthreads();
    for (int s = 128; s > 0; s >>= 1) { if (tid < s) red[tid] = fmaxf(red[tid], red[tid + s]); __syncthreads(); }
    mx = red[0];
    float s_, inv, d128;
    if (mx < 1e-30f) { s_ = 0.f; inv = 0.f; d128 = 0.f; }
    else { s_ = mx * (1.f / 127.f); inv = 1.f / s_; d128 = 128.f * inv; }
    cnt = 0;
    for (int k = tid; k < K; k += 256) {
        const float val = v[cnt++];
        const float i0 = rintf(val * inv);
        const float r  = fmaf(-i0, s_, val);
        const float i1 = rintf(r * d128);
        A0[(size_t)row * K + k] = (int8_t)(int)i0;
        A1[(size_t)row * K + k] = (int8_t)(int)i1;
    }
    if (tid == 0) sA[row] = s_;
}

// ---------------------------------------------------------------------------
// column abs-max of W [K, N]
// ---------------------------------------------------------------------------
__global__ void cmax_zero(float* cm) { cm[blockIdx.x * 256 + threadIdx.x] = 0.f; }

__global__ void cmax_k(const float* __restrict__ W, int N, int Kc, float* __restrict__ cm)
{
    const int n  = blockIdx.x * 256 + threadIdx.x;
    const int k0 = blockIdx.y * Kc;
    float mx = 0.f;
    #pragma unroll 4
    for (int k = k0; k < k0 + Kc; k++) mx = fmaxf(mx, fabsf(W[(size_t)k * N + n]));
    atomicMax((unsigned*)&cm[n], __float_as_uint(mx));
}

// ---------------------------------------------------------------------------
// quantB_t: fp32 W [K,N] -> transposed int8 planes B0,B1 [N][K], per-col scale.
// ---------------------------------------------------------------------------
__global__ void quantB_t(const float* __restrict__ W, int N, int K,
                         int8_t* __restrict__ B0, int8_t* __restrict__ B1)
{
    __shared__ float sm[64][129];
    const int tid = threadIdx.x;
    const int n0 = blockIdx.x * 128, k0 = blockIdx.y * 64;
    #pragma unroll
    for (int it = 0; it < 8; it++) {
        const int row = it * 8 + (tid >> 5);
        const int c4  = (tid & 31) * 4;
        float4 v = *reinterpret_cast<const float4*>(W + (size_t)(k0 + row) * N + n0 + c4);
        sm[row][c4 + 0] = v.x; sm[row][c4 + 1] = v.y;
        sm[row][c4 + 2] = v.z; sm[row][c4 + 3] = v.w;
    }
    __syncthreads();
    const int n  = tid >> 1;
    const int kh = (tid & 1) * 32;
    const float mx = g_cmax[n0 + n];
    float s_, inv, d128;
    if (mx < 1e-30f) { s_ = 0.f; inv = 0.f; d128 = 0.f; }
    else { s_ = mx * (1.f / 127.f); inv = 1.f / s_; d128 = 128.f * inv; }
    int8_t o0[32], o1[32];
    #pragma unroll
    for (int j = 0; j < 32; j++) {
        const float val = sm[kh + j][n];
        const float i0 = rintf(val * inv);
        const float r  = fmaf(-i0, s_, val);
        const float i1 = rintf(r * d128);
        o0[j] = (int8_t)(int)i0;
        o1[j] = (int8_t)(int)i1;
    }
    const size_t dst = (size_t)(n0 + n) * K + k0 + kh;
    *reinterpret_cast<uint4*>(B0 + dst)      = *reinterpret_cast<uint4*>(o0);
    *reinterpret_cast<uint4*>(B0 + dst + 16) = *reinterpret_cast<uint4*>(o0 + 16);
    *reinterpret_cast<uint4*>(B1 + dst)      = *reinterpret_cast<uint4*>(o1);
    *reinterpret_cast<uint4*>(B1 + dst + 16) = *reinterpret_cast<uint4*>(o1 + 16);
}

// ---------------------------------------------------------------------------
// int8 2-term GEMM, 2-stage cp.async ring (pattern identical to proven bf16 loop)
// ---------------------------------------------------------------------------
#define LDI     80
#define PLANE_I (128 * LDI)        // 10240
#define STAGE_I (4 * PLANE_I)      // 40960
#define NSTG_I  2

__global__ void __launch_bounds__(256, 1)
gemm_i8(const int8_t* __restrict__ A0g, const int8_t* __restrict__ A1g,
        const int8_t* __restrict__ B0g, const int8_t* __restrict__ B1g,
        const float* __restrict__ sA, const float* __restrict__ cmax,
        float* __restrict__ C, int N, int K)
{
    extern __shared__ char smbuf[];
    const uint32_t sb = smem_u32(smbuf);

    const int tid  = threadIdx.x;
    const int lane = tid & 31;
    const int wid  = tid >> 5;
    const int wm   = (wid & 3) * 32;
    const int wn   = (wid >> 2) * 64;
    const int m0   = blockIdx.y * 128, n0 = blockIdx.x * 128;
    const int KT   = K / 64;

    const int lr  = tid >> 1;
    const int lo2 = (tid & 1) * 32;

    const int8_t* gA0 = A0g + (size_t)(m0 + lr) * K + lo2;
    const int8_t* gA1 = A1g + (size_t)(m0 + lr) * K + lo2;
    const int8_t* gB0 = B0g + (size_t)(n0 + lr) * K + lo2;
    const int8_t* gB1 = B1g + (size_t)(n0 + lr) * K + lo2;

    auto load_stage = [&](int s, int c) {
        const uint32_t st = sb + s * STAGE_I;
        const size_t kk = (size_t)c * 64;
        const uint32_t d = st + lr * LDI + lo2;
        CP_ASYNC16(d,                    gA0 + kk);
        CP_ASYNC16(d + 16,               gA0 + kk + 16);
        CP_ASYNC16(d + PLANE_I,          gA1 + kk);
        CP_ASYNC16(d + PLANE_I + 16,     gA1 + kk + 16);
        CP_ASYNC16(d + 2 * PLANE_I,      gB0 + kk);
        CP_ASYNC16(d + 2 * PLANE_I + 16, gB0 + kk + 16);
        CP_ASYNC16(d + 3 * PLANE_I,      gB1 + kk);
        CP_ASYNC16(d + 3 * PLANE_I + 16, gB1 + kk + 16);
    };

    load_stage(0, 0); CP_COMMIT();
    load_stage(1, 1); CP_COMMIT();

    int accP[2][8][4], accX[2][8][4];
    #pragma unroll
    for (int i = 0; i < 2; i++)
        #pragma unroll
        for (int j = 0; j < 8; j++)
            #pragma unroll
            for (int r = 0; r < 4; r++) { accP[i][j][r] = 0; accX[i][j][r] = 0; }

    const int lrow = lane & 15;
    const int lkof = (lane >> 4) * 16;

    for (int c = 0; c < KT; c++) {
        CP_WAIT1();
        __syncthreads();
        const uint32_t st = sb + (c & 1) * STAGE_I;

        #pragma unroll
        for (int ks = 0; ks < 2; ks++) {
            const uint32_t koff = ks * 32 + lkof;
            uint32_t a0f[2][4], a1f[2][4];
            #pragma unroll
            for (int mt = 0; mt < 2; mt++) {
                const uint32_t aa = st + (wm + mt * 16 + lrow) * LDI + koff;
                LDSM_X4(a0f[mt][0], a0f[mt][1], a0f[mt][2], a0f[mt][3], aa);
                LDSM_X4(a1f[mt][0], a1f[mt][1], a1f[mt][2], a1f[mt][3], aa + PLANE_I);
            }
            uint32_t b0f[4][4], b1f[4][4];
            #pragma unroll
            for (int np = 0; np < 4; np++) {
                const uint32_t ba = st + 2 * PLANE_I + (wn + np * 16 + lrow) * LDI + koff;
                LDSM_X4(b0f[np][0], b0f[np][1], b0f[np][2], b0f[np][3], ba);
                LDSM_X4(b1f[np][0], b1f[np][1], b1f[np][2], b1f[np][3], ba + PLANE_I);
            }
            #pragma unroll
            for (int mt = 0; mt < 2; mt++) {
                #pragma unroll
                for (int np = 0; np < 4; np++) {
                    MMA_S8(accP[mt][np * 2 + 0], a0f[mt], b0f[np][0], b0f[np][2]);
                    MMA_S8(accP[mt][np * 2 + 1], a0f[mt], b0f[np][1], b0f[np][3]);
                    MMA_S8(accX[mt][np * 2 + 0], a0f[mt], b1f[np][0], b1f[np][2]);
                    MMA_S8(accX[mt][np * 2 + 1], a0f[mt], b1f[np][1], b1f[np][3]);
                    MMA_S8(accX[mt][np * 2 + 0], a1f[mt], b0f[np][0], b0f[np][2]);
                    MMA_S8(accX[mt][np * 2 + 1], a1f[mt], b0f[np][1], b0f[np][3]);
                }
            }
        }
        __syncthreads();
        if (c + 2 < KT) load_stage(c & 1, c + 2);
        CP_COMMIT();
    }

    const float r128 = 0.0078125f, i127 = 1.f / 127.f;
    #pragma unroll
    for (int mt = 0; mt < 2; mt++) {
        const int row = m0 + wm + mt * 16 + (lane >> 2);
        const float sa0 = sA[row], sa1 = sA[row + 8];
        #pragma unroll
        for (int g8 = 0; g8 < 8; g8++) {
            const int col = n0 + wn + g8 * 8 + (lane & 3) * 2;
            const float sb0 = cmax[col] * i127, sb1 = cmax[col + 1] * i127;
            float2 v0, v1;
            v0.x = sa0 * sb0 * fmaf((float)accX[mt][g8][0], r128, (float)accP[mt][g8][0]);
            v0.y = sa0 * sb1 * fmaf((float)accX[mt][g8][1], r128, (float)accP[mt][g8][1]);
            v1.x = sa1 * sb0 * fmaf((float)accX[mt][g8][2], r128, (float)accP[mt][g8][2]);
            v1.y = sa1 * sb1 * fmaf((float)accX[mt][g8][3], r128, (float)accP[mt][g8][3]);
            *reinterpret_cast<float2*>(C + (size_t)row * N + col) = v0;
            *reinterpret_cast<float2*>(C + (size_t)(row + 8) * N + col) = v1;
        }
    }
}

// ---------------------------------------------------------------------------
// rope_split (unchanged)
// ---------------------------------------------------------------------------
__global__ void rope_split_kernel(const float* __restrict__ fcos, const float* __restrict__ fsin)
{
    const int s   = blockIdx.x;
    const int tid = threadIdx.x;
    const float* crow = fcos + (size_t)s * 128;
    const float* srow = fsin + (size_t)s * 128;
    const float* row  = g_qkv + (size_t)s * QKV_N;

    for (int p = tid; p < NH * 128; p += 256) {
        const int h = p >> 7, d = p & 127;
        const float c = crow[d], sn = srow[d];
        const float x1 = row[h * HD + d], x2 = row[h * HD + d + 128];
        const float y1 = (x1 * c - x2 * sn) * SCALING;
        const float y2 = (x1 * sn + x2 * c) * SCALING;
        const size_t o = ((size_t)h * S_LEN + s) * HD + d;
        __nv_bfloat16 hh, ll;
        split_bf16(y1, hh, ll); g_Qh[o] = hh; g_Ql[o] = ll;
        split_bf16(y2, hh, ll); g_Qh[o + 128] = hh; g_Ql[o + 128] = ll;
    }
    for (int p = tid; p < NKV * 128; p += 256) {
        const int h = p >> 7, d = p & 127;
        const float c = crow[d], sn = srow[d];
        const float x1 = row[(NH + h) * HD + d], x2 = row[(NH + h) * HD + d + 128];
        const float y1 = x1 * c - x2 * sn;
        const float y2 = x1 * sn + x2 * c;
        const size_t o = ((size_t)h * S_LEN + s) * HD + d;
        __nv_bfloat16 hh, ll;
        split_bf16(y1, hh, ll); g_Kh[o] = hh; g_Kl[o] = ll;
        split_bf16(y2, hh, ll); g_Kh[o + 128] = hh; g_Kl[o + 128] = ll;
    }
    for (int p = tid; p < NKV * HD; p += 256) {
        const int h = p >> 8, d = p & 255;
        const float v = row[(NH + NKV + h) * HD + d];
        const size_t o = ((size_t)h * S_LEN + s) * HD + d;
        __nv_bfloat16 hh, ll;
        split_bf16(v, hh, ll); g_Vh[o] = hh; g_Vl[o] = ll;
    }
}

// ---------------------------------------------------------------------------
// Tensor-core flash attention (split-bf16). Epilogue -> fp32 g_attn.
// ---------------------------------------------------------------------------
#define SROWB 528
#define QPLANE (64 * SROWB)
#define KVPLANE (32 * SROWB)
#define KVSTAGE (4 * KVPLANE)

__global__ void __launch_bounds__(128, 1) attn_mma_kernel()
{
    extern __shared__ char smv[];
    const uint32_t sb = smem_u32(smv);
    const uint32_t QH = sb, QL = sb + QPLANE, ST0 = sb + 2 * QPLANE;

    const int tid  = threadIdx.x;
    const int lane = tid & 31;
    const int wq   = tid >> 5;
    const int q0   = blockIdx.x * 64;
    const int h    = blockIdx.y;
    const int kvh  = h >> 1;

    const int lrow  = lane & 15;
    const int lcolb = (lane >> 4) * 16;
    const int g     = lane >> 2;
    const int t2    = (lane & 3) * 2;

    const __nv_bfloat16* pQh = g_Qh + ((size_t)h * S_LEN + q0) * HD;
    const __nv_bfloat16* pQl = g_Ql + ((size_t)h * S_LEN + q0) * HD;
    const __nv_bfloat16* bKh = g_Kh + (size_t)kvh * S_LEN * HD;
    const __nv_bfloat16* bKl = g_Kl + (size_t)kvh * S_LEN * HD;
    const __nv_bfloat16* bVh = g_Vh + (size_t)kvh * S_LEN * HD;
    const __nv_bfloat16* bVl = g_Vl + (size_t)kvh * S_LEN * HD;

    for (int i = tid; i < 64 * 32; i += 128) {
        const int r = i >> 5, ch = i & 31;
        const uint32_t o = (uint32_t)r * SROWB + ch * 16;
        const size_t go = (size_t)r * HD + ch * 8;
        CP_ASYNC16(QH + o, pQh + go);
        CP_ASYNC16(QL + o, pQl + go);
    }

    auto load_kv = [&](int s, int kb) {
        const uint32_t base = ST0 + s * KVSTAGE;
        for (int i = tid; i < 32 * 32; i += 128) {
            const int r = i >> 5, ch = i & 31;
            const uint32_t o = (uint32_t)r * SROWB + ch * 16;
            const size_t go = (size_t)(kb + r) * HD + ch * 8;
            CP_ASYNC16(base + o,               bKh + go);
            CP_ASYNC16(base + KVPLANE + o,     bKl + go);
            CP_ASYNC16(base + 2 * KVPLANE + o, bVh + go);
            CP_ASYNC16(base + 3 * KVPLANE + o, bVl + go);
        }
    };

    const int klo = (q0 - (WIN - 1)) > 0 ? (q0 - (WIN - 1)) : 0;
    const int kb0 = klo & ~31;
    const int nch = (q0 + 64 - kb0) >> 5;

    load_kv(0, kb0); CP_COMMIT();
    if (nch > 1) load_kv(1, kb0 + 32);
    CP_COMMIT();

    float o[32][4];
    #pragma unroll
    for (int i = 0; i < 32; i++)
        #pragma unroll
        for (int r = 0; r < 4; r++) o[i][r] = 0.f;
    float rs0 = 0.f, rs1 = 0.f;
    const int qrow0 = q0 + wq * 16 + g;

    for (int ic = 0; ic < nch; ic++) {
        const int kb = kb0 + ic * 32;
        CP_WAIT1();
        __syncthreads();
        const uint32_t st = ST0 + (ic & 1) * KVSTAGE;

        float sf[4][4];
        #pragma unroll
        for (int t = 0; t < 4; t++)
            #pragma unroll
            for (int r = 0; r < 4; r++) sf[t][r] = 0.f;

        #pragma unroll
        for (int dc = 0; dc < 16; dc++) {
            const uint32_t qa = QH + (uint32_t)(wq * 16 + lrow) * SROWB + dc * 32 + lcolb;
            uint32_t ah[4], al[4];
            LDSM_X4(ah[0], ah[1], ah[2], ah[3], qa);
            LDSM_X4(al[0], al[1], al[2], al[3], qa + QPLANE);
            #pragma unroll
            for (int kg = 0; kg < 2; kg++) {
                const uint32_t ka = st + (uint32_t)(kg * 16 + lrow) * SROWB + dc * 32 + lcolb;
                uint32_t bh[4], bl[4];
                LDSM_X4(bh[0], bh[1], bh[2], bh[3], ka);
                LDSM_X4(bl[0], bl[1], bl[2], bl[3], ka + KVPLANE);
                MMA_BF16(sf[kg * 2 + 0], ah, bh[0], bh[2]);
                MMA_BF16(sf[kg * 2 + 1], ah, bh[1], bh[3]);
                MMA_BF16(sf[kg * 2 + 0], ah, bl[0], bl[2]);
                MMA_BF16(sf[kg * 2 + 1], ah, bl[1], bl[3]);
                MMA_BF16(sf[kg * 2 + 0], al, bh[0], bh[2]);
                MMA_BF16(sf[kg * 2 + 1], al, bh[1], bh[3]);
            }
        }

        uint32_t ph[4][2], pl[4][2];
        #pragma unroll
        for (int t = 0; t < 4; t++) {
            const int kcol = kb + t * 8 + t2;
            float pv[4];
            #pragma unroll
            for (int r = 0; r < 4; r++) {
                const int q = qrow0 + ((r >= 2) ? 8 : 0);
                const int k = kcol + (r & 1);
                const float u = __expf(0.04f * sf[t][r]);
                const float p = __expf(__fdividef(-100.f, u + 1.f));
                pv[r] = (k <= q && (q - k) < WIN) ? p : 0.f;
            }
            rs0 += pv[0] + pv[1];
            rs1 += pv[2] + pv[3];
            split2(pv[0], pv[1], ph[t][0], pl[t][0]);
            split2(pv[2], pv[3], ph[t][1], pl[t][1]);
        }

        #pragma unroll
        for (int kg = 0; kg < 2; kg++) {
            uint32_t pah[4] = { ph[kg * 2][0], ph[kg * 2][1], ph[kg * 2 + 1][0], ph[kg * 2 + 1][1] };
            uint32_t pal[4] = { pl[kg * 2][0], pl[kg * 2][1], pl[kg * 2 + 1][0], pl[kg * 2 + 1][1] };
            #pragma unroll
            for (int dc = 0; dc < 16; dc++) {
                const uint32_t va = st + 2 * KVPLANE +
                    (uint32_t)(kg * 16 + lrow) * SROWB + dc * 32 + lcolb;
                uint32_t vh[4], vl[4];
                LDSM_X4T(vh[0], vh[1], vh[2], vh[3], va);
                LDSM_X4T(vl[0], vl[1], vl[2], vl[3], va + KVPLANE);
                MMA_BF16(o[dc * 2 + 0], pah, vh[0], vh[1]);
                MMA_BF16(o[dc * 2 + 1], pah, vh[2], vh[3]);
                MMA_BF16(o[dc * 2 + 0], pah, vl[0], vl[1]);
                MMA_BF16(o[dc * 2 + 1], pah, vl[2], vl[3]);
                MMA_BF16(o[dc * 2 + 0], pal, vh[0], vh[1]);
                MMA_BF16(o[dc * 2 + 1], pal, vh[2], vh[3]);
            }
        }
        __syncthreads();
        if (ic + 2 < nch) load_kv(ic & 1, kb + 64);
        CP_COMMIT();
    }

    rs0 += __shfl_xor_sync(0xFFFFFFFFu, rs0, 1);
    rs0 += __shfl_xor_sync(0xFFFFFFFFu, rs0, 2);
    rs1 += __shfl_xor_sync(0xFFFFFFFFu, rs1, 1);
    rs1 += __shfl_xor_sync(0xFFFFFFFFu, rs1, 2);
    const float i0 = 1.0f / rs0, i1 = 1.0f / rs1;

    const int row0 = q0 + wq * 16 + g;
    #pragma unroll
    for (int t = 0; t < 32; t++) {
        const int col = h * HD + (t >> 1) * 16 + (t & 1) * 8 + t2;
        float2 v0 = make_float2(o[t][0] * i0, o[t][1] * i0);
        float2 v1 = make_float2(o[t][2] * i1, o[t][3] * i1);
        *reinterpret_cast<float2*>(&g_attn[(size_t)row0 * ATTN_N + col]) = v0;
        *reinterpret_cast<float2*>(&g_attn[(size_t)(row0 + 8) * ATTN_N + col]) = v1;
    }
}

// ---------------------------------------------------------------------------
extern "C" void kernel_launch(void* const* d_in, const int* in_sizes, int n_in,
                              void* d_out, int out_size)
{
    const float* hidden = (const float*)d_in[0];
    const float* Wqkv   = (const float*)d_in[1];
    const float* Wo     = (const float*)d_in[2];
    const float* fcos   = (const float*)d_in[3];
    const float* fsin   = (const float*)d_in[4];
    float* out = (float*)d_out;

    float *qkv_ptr, *attn_ptr, *sA_ptr, *cmax_ptr;
    int8_t *A0, *A1, *B0, *B1;
    cudaGetSymbolAddress((void**)&qkv_ptr,  g_qkv);
    cudaGetSymbolAddress((void**)&attn_ptr, g_attn);
    cudaGetSymbolAddress((void**)&A0, g_iA0);
    cudaGetSymbolAddress((void**)&A1, g_iA1);
    cudaGetSymbolAddress((void**)&B0, g_iB0);
    cudaGetSymbolAddress((void**)&B1, g_iB1);
    cudaGetSymbolAddress((void**)&sA_ptr, g_sA);
    cudaGetSymbolAddress((void**)&cmax_ptr, g_cmax);

    const int gemm_smem = NSTG_I * STAGE_I;               // 81920
    const int attn_smem = 2 * QPLANE + 2 * KVSTAGE;       // 202752
    cudaFuncSetAttribute(gemm_i8, cudaFuncAttributeMaxDynamicSharedMemorySize, gemm_smem);
    cudaFuncSetAttribute(attn_mma_kernel, cudaFuncAttributeMaxDynamicSharedMemorySize, attn_smem);

    // ---- QKV projection (int8 2-term): [2048,3584] @ [3584,8192] ----
    quant_rows<<<S_LEN, 256>>>(hidden, HID_DIM, A0, A1, sA_ptr);
    cmax_zero<<<QKV_N / 256, 256>>>(cmax_ptr);
    cmax_k<<<dim3(QKV_N / 256, 16), 256>>>(Wqkv, QKV_N, HID_DIM / 16, cmax_ptr);
    quantB_t<<<dim3(QKV_N / 128, HID_DIM / 64), 256>>>(Wqkv, QKV_N, HID_DIM, B0, B1);
    gemm_i8<<<dim3(QKV_N / 128, S_LEN / 128), 256, gemm_smem>>>(
        A0, A1, B0, B1, sA_ptr, cmax_ptr, qkv_ptr, QKV_N, HID_DIM);

    // ---- RoPE + split to bf16 head planes ----
    rope_split_kernel<<<S_LEN, 256>>>(fcos, fsin);

    // ---- Attention (bf16 split), writes fp32 g_attn ----
    attn_mma_kernel<<<dim3(S_LEN / 64, NH), 128, attn_smem>>>();

    // ---- Output projection (int8 2-term): [2048,4096] @ [4096,3584] ----
    quant_rows<<<S_LEN, 256>>>(attn_ptr, ATTN_N, A0, A1, sA_ptr);
    cmax_zero<<<HID_DIM / 256, 256>>>(cmax_ptr);
    cmax_k<<<dim3(HID_DIM / 256, 16), 256>>>(Wo, HID_DIM, ATTN_N / 16, cmax_ptr);
    quantB_t<<<dim3(HID_DIM / 128, ATTN_N / 64), 256>>>(Wo, HID_DIM, ATTN_N, B0, B1);
    gemm_i8<<<dim3(HID_DIM / 128, S_LEN / 128), 256, gemm_smem>>>(
        A0, A1, B0, B1, sA_ptr, cmax_ptr, out, HID_DIM, ATTN_N);
}

// round 9
// speedup vs baseline: 1.9832x; 1.9832x over previous
#include <cuda_runtime.h>
#include <cuda_bf16.h>
#include <math.h>
#include <stdint.h>

#define S_LEN   2048
#define HID_DIM 3584
#define NH      16
#define NKV     8
#define HD      256
#define QKV_N   ((NH + 2 * NKV) * HD)   // 8192
#define ATTN_N  (NH * HD)               // 4096
#define WIN     1024
#define SOFTCAP 50.0f
#define SCALING 0.0625f

// ---------------- scratch (__device__ globals; no allocs allowed) ----------
__device__ __align__(256) float g_qkv[S_LEN * QKV_N];    // 64 MB
__device__ __align__(256) __nv_bfloat16 g_Ah[S_LEN * 4096];
__device__ __align__(256) __nv_bfloat16 g_Al[S_LEN * 4096];
__device__ __align__(256) __nv_bfloat16 g_Bh[8192 * 3584];
__device__ __align__(256) __nv_bfloat16 g_Bl[8192 * 3584];
// per-head bf16 planes for attention
__device__ __align__(256) __nv_bfloat16 g_Qh[NH  * S_LEN * HD];
__device__ __align__(256) __nv_bfloat16 g_Ql[NH  * S_LEN * HD];
__device__ __align__(256) __nv_bfloat16 g_Kh[NKV * S_LEN * HD];
__device__ __align__(256) __nv_bfloat16 g_Kl[NKV * S_LEN * HD];
__device__ __align__(256) __nv_bfloat16 g_Vh[NKV * S_LEN * HD];
__device__ __align__(256) __nv_bfloat16 g_Vl[NKV * S_LEN * HD];

// ---------------- PTX helpers ----------------------------------------------
__device__ __forceinline__ uint32_t smem_u32(const void* p) {
    uint32_t a;
    asm("{ .reg .u64 t; cvta.to.shared.u64 t, %1; cvt.u32.u64 %0, t; }" : "=r"(a) : "l"(p));
    return a;
}
#define CP_ASYNC16(dst, src) \
    asm volatile("cp.async.cg.shared.global [%0], [%1], 16;" :: "r"(dst), "l"(src) : "memory")
#define CP_COMMIT() asm volatile("cp.async.commit_group;" ::: "memory")
#define CP_WAIT1()  asm volatile("cp.async.wait_group 1;" ::: "memory")

#define LDSM_X4(r0, r1, r2, r3, addr) \
    asm volatile("ldmatrix.sync.aligned.m8n8.x4.shared.b16 {%0,%1,%2,%3}, [%4];" \
        : "=r"(r0), "=r"(r1), "=r"(r2), "=r"(r3) : "r"(addr))
#define LDSM_X4T(r0, r1, r2, r3, addr) \
    asm volatile("ldmatrix.sync.aligned.m8n8.x4.trans.shared.b16 {%0,%1,%2,%3}, [%4];" \
        : "=r"(r0), "=r"(r1), "=r"(r2), "=r"(r3) : "r"(addr))

#define MMA_BF16(d, a, b0, b1) \
    asm volatile("mma.sync.aligned.m16n8k16.row.col.f32.bf16.bf16.f32 " \
        "{%0,%1,%2,%3}, {%4,%5,%6,%7}, {%8,%9}, {%0,%1,%2,%3};" \
        : "+f"((d)[0]), "+f"((d)[1]), "+f"((d)[2]), "+f"((d)[3]) \
        : "r"((a)[0]), "r"((a)[1]), "r"((a)[2]), "r"((a)[3]), "r"(b0), "r"(b1))

__device__ __forceinline__ void split_bf16(float x, __nv_bfloat16& h, __nv_bfloat16& l) {
    h = __float2bfloat16_rn(x);
    l = __float2bfloat16_rn(x - __bfloat162float(h));
}
__device__ __forceinline__ void split2(float a, float b, uint32_t& hi, uint32_t& lo) {
    __nv_bfloat16 ha, la, hb, lb;
    split_bf16(a, ha, la); split_bf16(b, hb, lb);
    __nv_bfloat162 H; H.x = ha; H.y = hb;
    __nv_bfloat162 L; L.x = la; L.y = lb;
    hi = *reinterpret_cast<uint32_t*>(&H);
    lo = *reinterpret_cast<uint32_t*>(&L);
}

// ---------------------------------------------------------------------------
// conv_split: fp32 row-major -> hi/lo bf16, same layout. 4 elems/thread.
// ---------------------------------------------------------------------------
__global__ void conv_split(const float4* __restrict__ X, __nv_bfloat162* __restrict__ H,
                           __nv_bfloat162* __restrict__ L)
{
    const size_t i = (size_t)blockIdx.x * blockDim.x + threadIdx.x;
    float4 v = X[i];
    __nv_bfloat16 h0, l0, h1, l1, h2, l2, h3, l3;
    split_bf16(v.x, h0, l0); split_bf16(v.y, h1, l1);
    split_bf16(v.z, h2, l2); split_bf16(v.w, h3, l3);
    __nv_bfloat162 a, b, c, d;
    a.x = h0; a.y = h1;  b.x = h2; b.y = h3;
    c.x = l0; c.y = l1;  d.x = l2; d.y = l3;
    H[2 * i] = a; H[2 * i + 1] = b;
    L[2 * i] = c; L[2 * i + 1] = d;
}

// ---------------------------------------------------------------------------
// HMMA split-bf16 GEMM (R4 proven config: 8 warps 32x64, 2-stage)
// ---------------------------------------------------------------------------
#define BM   128
#define BN   128
#define BK   32
#define LDA  40
#define LDB  136
#define TILE_A_B (128 * LDA * 2)
#define TILE_B_B (32 * LDB * 2)
#define OFF_AH   0
#define OFF_AL   (TILE_A_B)
#define OFF_BH   (2 * TILE_A_B)
#define OFF_BL   (2 * TILE_A_B + TILE_B_B)
#define STAGE_B  (2 * TILE_A_B + 2 * TILE_B_B)
#define NSTG 2

__global__ void __launch_bounds__(256, 1)
gemm_mma(const __nv_bfloat16* __restrict__ Ah, const __nv_bfloat16* __restrict__ Al,
         const __nv_bfloat16* __restrict__ Bh, const __nv_bfloat16* __restrict__ Bl,
         float* __restrict__ C, int N, int K)
{
    extern __shared__ char smbuf[];
    const uint32_t sb = smem_u32(smbuf);

    const int tid  = threadIdx.x;
    const int lane = tid & 31;
    const int wid  = tid >> 5;
    const int wm   = (wid & 3) * 32;
    const int wn   = (wid >> 2) * 64;
    const int nb   = blockIdx.x, mbk = blockIdx.y;
    const int m0   = mbk * BM, n0 = nb * BN;
    const int KT   = K / BK;

    const int ar = tid >> 1, ac = (tid & 1) * 16;
    const int br = tid >> 3, bc = (tid & 7) * 16;

    const __nv_bfloat16* gAh = Ah + (size_t)(m0 + ar) * K + ac;
    const __nv_bfloat16* gAl = Al + (size_t)(m0 + ar) * K + ac;
    const __nv_bfloat16* gBh = Bh + (size_t)br * N + n0 + bc;
    const __nv_bfloat16* gBl = Bl + (size_t)br * N + n0 + bc;

    auto load_stage = [&](int s, int c) {
        const uint32_t st = sb + s * STAGE_B;
        const size_t ka = (size_t)c * BK;
        const uint32_t sa = st + (ar * LDA + ac) * 2;
        CP_ASYNC16(sa + OFF_AH,      gAh + ka);
        CP_ASYNC16(sa + OFF_AH + 16, gAh + ka + 8);
        CP_ASYNC16(sa + OFF_AL,      gAl + ka);
        CP_ASYNC16(sa + OFF_AL + 16, gAl + ka + 8);
        const uint32_t sbm = st + (br * LDB + bc) * 2;
        const size_t kb = (size_t)c * BK * N;
        CP_ASYNC16(sbm + OFF_BH,      gBh + kb);
        CP_ASYNC16(sbm + OFF_BH + 16, gBh + kb + 8);
        CP_ASYNC16(sbm + OFF_BL,      gBl + kb);
        CP_ASYNC16(sbm + OFF_BL + 16, gBl + kb + 8);
    };

    load_stage(0, 0); CP_COMMIT();
    load_stage(1, 1); CP_COMMIT();

    float d[2][8][4];
    #pragma unroll
    for (int i = 0; i < 2; i++)
        #pragma unroll
        for (int j = 0; j < 8; j++)
            #pragma unroll
            for (int r = 0; r < 4; r++) d[i][j][r] = 0.f;

    const int lrow = lane & 15;
    const int lcol = (lane >> 4) * 8;

    for (int c = 0; c < KT; c++) {
        CP_WAIT1();
        __syncthreads();
        const uint32_t st = sb + (c & 1) * STAGE_B;

        #pragma unroll
        for (int ks = 0; ks < 2; ks++) {
            uint32_t ah[2][4], al[2][4];
            #pragma unroll
            for (int mb = 0; mb < 2; mb++) {
                const uint32_t aoff = st + ((wm + mb * 16 + lrow) * LDA + ks * 16 + lcol) * 2;
                LDSM_X4(ah[mb][0], ah[mb][1], ah[mb][2], ah[mb][3], aoff + OFF_AH);
                LDSM_X4(al[mb][0], al[mb][1], al[mb][2], al[mb][3], aoff + OFF_AL);
            }
            uint32_t bh[4][4], bl[4][4];
            #pragma unroll
            for (int ng = 0; ng < 4; ng++) {
                const uint32_t boff = st + ((ks * 16 + lrow) * LDB + wn + ng * 16 + lcol) * 2;
                LDSM_X4T(bh[ng][0], bh[ng][1], bh[ng][2], bh[ng][3], boff + OFF_BH);
                LDSM_X4T(bl[ng][0], bl[ng][1], bl[ng][2], bl[ng][3], boff + OFF_BL);
            }
            #pragma unroll
            for (int mb = 0; mb < 2; mb++) {
                #pragma unroll
                for (int ng = 0; ng < 4; ng++) {
                    MMA_BF16(d[mb][ng * 2 + 0], ah[mb], bh[ng][0], bh[ng][1]);
                    MMA_BF16(d[mb][ng * 2 + 1], ah[mb], bh[ng][2], bh[ng][3]);
                    MMA_BF16(d[mb][ng * 2 + 0], ah[mb], bl[ng][0], bl[ng][1]);
                    MMA_BF16(d[mb][ng * 2 + 1], ah[mb], bl[ng][2], bl[ng][3]);
                    MMA_BF16(d[mb][ng * 2 + 0], al[mb], bh[ng][0], bh[ng][1]);
                    MMA_BF16(d[mb][ng * 2 + 1], al[mb], bh[ng][2], bh[ng][3]);
                }
            }
        }
        __syncthreads();
        if (c + 2 < KT) load_stage(c & 1, c + 2);
        CP_COMMIT();
    }

    #pragma unroll
    for (int mb = 0; mb < 2; mb++) {
        const int row = m0 + wm + mb * 16 + (lane >> 2);
        #pragma unroll
        for (int nb8 = 0; nb8 < 8; nb8++) {
            const int col = n0 + wn + nb8 * 8 + (lane & 3) * 2;
            float2 v0 = make_float2(d[mb][nb8][0], d[mb][nb8][1]);
            float2 v1 = make_float2(d[mb][nb8][2], d[mb][nb8][3]);
            *reinterpret_cast<float2*>(C + (size_t)row * N + col) = v0;
            *reinterpret_cast<float2*>(C + (size_t)(row + 8) * N + col) = v1;
        }
    }
}

// ---------------------------------------------------------------------------
// rope_split: rope Q (scaled) and K, split Q/K/V into hi/lo bf16 head-planes.
// ---------------------------------------------------------------------------
__global__ void rope_split_kernel(const float* __restrict__ fcos, const float* __restrict__ fsin)
{
    const int s   = blockIdx.x;
    const int tid = threadIdx.x;
    const float* crow = fcos + (size_t)s * 128;
    const float* srow = fsin + (size_t)s * 128;
    const float* row  = g_qkv + (size_t)s * QKV_N;

    for (int p = tid; p < NH * 128; p += 256) {
        const int h = p >> 7, d = p & 127;
        const float c = crow[d], sn = srow[d];
        const float x1 = row[h * HD + d], x2 = row[h * HD + d + 128];
        const float y1 = (x1 * c - x2 * sn) * SCALING;
        const float y2 = (x1 * sn + x2 * c) * SCALING;
        const size_t o = ((size_t)h * S_LEN + s) * HD + d;
        __nv_bfloat16 hh, ll;
        split_bf16(y1, hh, ll); g_Qh[o] = hh; g_Ql[o] = ll;
        split_bf16(y2, hh, ll); g_Qh[o + 128] = hh; g_Ql[o + 128] = ll;
    }
    for (int p = tid; p < NKV * 128; p += 256) {
        const int h = p >> 7, d = p & 127;
        const float c = crow[d], sn = srow[d];
        const float x1 = row[(NH + h) * HD + d], x2 = row[(NH + h) * HD + d + 128];
        const float y1 = x1 * c - x2 * sn;
        const float y2 = x1 * sn + x2 * c;
        const size_t o = ((size_t)h * S_LEN + s) * HD + d;
        __nv_bfloat16 hh, ll;
        split_bf16(y1, hh, ll); g_Kh[o] = hh; g_Kl[o] = ll;
        split_bf16(y2, hh, ll); g_Kh[o + 128] = hh; g_Kl[o + 128] = ll;
    }
    for (int p = tid; p < NKV * HD; p += 256) {
        const int h = p >> 8, d = p & 255;
        const float v = row[(NH + NKV + h) * HD + d];
        const size_t o = ((size_t)h * S_LEN + s) * HD + d;
        __nv_bfloat16 hh, ll;
        split_bf16(v, hh, ll); g_Vh[o] = hh; g_Vl[o] = ll;
    }
}

// ---------------------------------------------------------------------------
// Tensor-core flash attention, 8 warps: warp-pair splits each 32-k chunk.
// wq = wid>>1 (16 q rows), kg = wid&1 (16-k half). Partial O reduced once at
// the end through the dead KV smem stage; row sums via smem atomicAdd.
// ---------------------------------------------------------------------------
#define SROWB 528
#define QPLANE (64 * SROWB)
#define KVPLANE (32 * SROWB)
#define KVSTAGE (4 * KVPLANE)
#define ATTN_SMEM (2 * QPLANE + 2 * KVSTAGE + 256)

__global__ void __launch_bounds__(256, 1) attn_mma_kernel()
{
    extern __shared__ char smv[];
    const uint32_t sb = smem_u32(smv);
    const uint32_t QH = sb, QL = sb + QPLANE, ST0 = sb + 2 * QPLANE;
    float* sSum = reinterpret_cast<float*>(smv + 2 * QPLANE + 2 * KVSTAGE);

    const int tid  = threadIdx.x;
    const int lane = tid & 31;
    const int wid  = tid >> 5;
    const int wq   = wid >> 1;     // q-group: 16 rows
    const int kg   = wid & 1;      // k-half: 16 cols of the 32-k chunk
    const int q0   = blockIdx.x * 64;
    const int h    = blockIdx.y;
    const int kvh  = h >> 1;

    const int lrow  = lane & 15;
    const int lcolb = (lane >> 4) * 16;
    const int g     = lane >> 2;
    const int t2    = (lane & 3) * 2;

    if (tid < 64) sSum[tid] = 0.f;

    const __nv_bfloat16* pQh = g_Qh + ((size_t)h * S_LEN + q0) * HD;
    const __nv_bfloat16* pQl = g_Ql + ((size_t)h * S_LEN + q0) * HD;
    const __nv_bfloat16* bKh = g_Kh + (size_t)kvh * S_LEN * HD;
    const __nv_bfloat16* bKl = g_Kl + (size_t)kvh * S_LEN * HD;
    const __nv_bfloat16* bVh = g_Vh + (size_t)kvh * S_LEN * HD;
    const __nv_bfloat16* bVl = g_Vl + (size_t)kvh * S_LEN * HD;

    for (int i = tid; i < 64 * 32; i += 256) {
        const int r = i >> 5, ch = i & 31;
        const uint32_t o = (uint32_t)r * SROWB + ch * 16;
        const size_t go = (size_t)r * HD + ch * 8;
        CP_ASYNC16(QH + o, pQh + go);
        CP_ASYNC16(QL + o, pQl + go);
    }

    auto load_kv = [&](int s, int kb) {
        const uint32_t base = ST0 + s * KVSTAGE;
        for (int i = tid; i < 32 * 32; i += 256) {
            const int r = i >> 5, ch = i & 31;
            const uint32_t o = (uint32_t)r * SROWB + ch * 16;
            const size_t go = (size_t)(kb + r) * HD + ch * 8;
            CP_ASYNC16(base + o,               bKh + go);
            CP_ASYNC16(base + KVPLANE + o,     bKl + go);
            CP_ASYNC16(base + 2 * KVPLANE + o, bVh + go);
            CP_ASYNC16(base + 3 * KVPLANE + o, bVl + go);
        }
    };

    const int klo = (q0 - (WIN - 1)) > 0 ? (q0 - (WIN - 1)) : 0;
    const int kb0 = klo & ~31;
    const int nch = (q0 + 64 - kb0) >> 5;

    load_kv(0, kb0); CP_COMMIT();
    if (nch > 1) load_kv(1, kb0 + 32);
    CP_COMMIT();

    float o[32][4];
    #pragma unroll
    for (int i = 0; i < 32; i++)
        #pragma unroll
        for (int r = 0; r < 4; r++) o[i][r] = 0.f;
    float rs0 = 0.f, rs1 = 0.f;
    const int qrow0 = q0 + wq * 16 + g;

    for (int ic = 0; ic < nch; ic++) {
        const int kb = kb0 + ic * 32;
        CP_WAIT1();
        __syncthreads();
        const uint32_t st = ST0 + (ic & 1) * KVSTAGE;

        // ---- S = Q K^T for this warp's 16-k half ----
        float sf[2][4];
        #pragma unroll
        for (int t = 0; t < 2; t++)
            #pragma unroll
            for (int r = 0; r < 4; r++) sf[t][r] = 0.f;

        #pragma unroll
        for (int dc = 0; dc < 16; dc++) {
            const uint32_t qa = QH + (uint32_t)(wq * 16 + lrow) * SROWB + dc * 32 + lcolb;
            uint32_t ah[4], al[4];
            LDSM_X4(ah[0], ah[1], ah[2], ah[3], qa);
            LDSM_X4(al[0], al[1], al[2], al[3], qa + QPLANE);
            const uint32_t ka = st + (uint32_t)(kg * 16 + lrow) * SROWB + dc * 32 + lcolb;
            uint32_t bh[4], bl[4];
            LDSM_X4(bh[0], bh[1], bh[2], bh[3], ka);
            LDSM_X4(bl[0], bl[1], bl[2], bl[3], ka + KVPLANE);
            MMA_BF16(sf[0], ah, bh[0], bh[2]);
            MMA_BF16(sf[1], ah, bh[1], bh[3]);
            MMA_BF16(sf[0], ah, bl[0], bl[2]);
            MMA_BF16(sf[1], ah, bl[1], bl[3]);
            MMA_BF16(sf[0], al, bh[0], bh[2]);
            MMA_BF16(sf[1], al, bh[1], bh[3]);
        }

        // ---- softcap + mask + exp(t-50): exp(-100/(e^{s/25}+1)) ----
        uint32_t ph[2][2], pl[2][2];
        #pragma unroll
        for (int t = 0; t < 2; t++) {
            const int kcol = kb + kg * 16 + t * 8 + t2;
            float pv[4];
            #pragma unroll
            for (int r = 0; r < 4; r++) {
                const int q = qrow0 + ((r >= 2) ? 8 : 0);
                const int k = kcol + (r & 1);
                const float u = __expf(0.04f * sf[t][r]);
                const float p = __expf(__fdividef(-100.f, u + 1.f));
                pv[r] = (k <= q && (q - k) < WIN) ? p : 0.f;
            }
            rs0 += pv[0] + pv[1];
            rs1 += pv[2] + pv[3];
            split2(pv[0], pv[1], ph[t][0], pl[t][0]);
            split2(pv[2], pv[3], ph[t][1], pl[t][1]);
        }

        // ---- O += P V over this warp's 16-k half ----
        uint32_t pah[4] = { ph[0][0], ph[0][1], ph[1][0], ph[1][1] };
        uint32_t pal[4] = { pl[0][0], pl[0][1], pl[1][0], pl[1][1] };
        #pragma unroll
        for (int dc = 0; dc < 16; dc++) {
            const uint32_t va = st + 2 * KVPLANE +
                (uint32_t)(kg * 16 + lrow) * SROWB + dc * 32 + lcolb;
            uint32_t vh[4], vl[4];
            LDSM_X4T(vh[0], vh[1], vh[2], vh[3], va);
            LDSM_X4T(vl[0], vl[1], vl[2], vl[3], va + KVPLANE);
            MMA_BF16(o[dc * 2 + 0], pah, vh[0], vh[1]);
            MMA_BF16(o[dc * 2 + 1], pah, vh[2], vh[3]);
            MMA_BF16(o[dc * 2 + 0], pah, vl[0], vl[1]);
            MMA_BF16(o[dc * 2 + 1], pah, vl[2], vl[3]);
            MMA_BF16(o[dc * 2 + 0], pal, vh[0], vh[1]);
            MMA_BF16(o[dc * 2 + 1], pal, vh[2], vh[3]);
        }
        __syncthreads();
        if (ic + 2 < nch) load_kv(ic & 1, kb + 64);
        CP_COMMIT();
    }

    // ---- row sums: intra-warp quad reduce, then cross-warp via smem ----
    rs0 += __shfl_xor_sync(0xFFFFFFFFu, rs0, 1);
    rs0 += __shfl_xor_sync(0xFFFFFFFFu, rs0, 2);
    rs1 += __shfl_xor_sync(0xFFFFFFFFu, rs1, 1);
    rs1 += __shfl_xor_sync(0xFFFFFFFFu, rs1, 2);
    if ((lane & 3) == 0) {
        atomicAdd(&sSum[wq * 16 + g], rs0);
        atomicAdd(&sSum[wq * 16 + g + 8], rs1);
    }

    // ---- O reduction across the warp pair via the dead KV stage ----
    float* red = reinterpret_cast<float*>(smv + 2 * QPLANE + (nch & 1) * KVSTAGE);
    if (kg == 1) {
        #pragma unroll
        for (int t = 0; t < 32; t++) {
            const int c  = (t >> 1) * 16 + (t & 1) * 8 + t2;
            const int r0 = wq * 16 + g;
            *reinterpret_cast<float2*>(&red[(size_t)r0 * 256 + c])       = make_float2(o[t][0], o[t][1]);
            *reinterpret_cast<float2*>(&red[(size_t)(r0 + 8) * 256 + c]) = make_float2(o[t][2], o[t][3]);
        }
    }
    __syncthreads();
    if (kg == 0) {
        const float i0 = 1.0f / sSum[wq * 16 + g];
        const float i1 = 1.0f / sSum[wq * 16 + g + 8];
        const int row0 = q0 + wq * 16 + g;
        const int rl   = wq * 16 + g;
        #pragma unroll
        for (int t = 0; t < 32; t++) {
            const int c   = (t >> 1) * 16 + (t & 1) * 8 + t2;
            const int col = h * HD + c;
            float2 p0 = *reinterpret_cast<float2*>(&red[(size_t)rl * 256 + c]);
            float2 p1 = *reinterpret_cast<float2*>(&red[(size_t)(rl + 8) * 256 + c]);
            uint32_t hi, lo;
            split2((o[t][0] + p0.x) * i0, (o[t][1] + p0.y) * i0, hi, lo);
            *reinterpret_cast<uint32_t*>(&g_Ah[(size_t)row0 * ATTN_N + col]) = hi;
            *reinterpret_cast<uint32_t*>(&g_Al[(size_t)row0 * ATTN_N + col]) = lo;
            split2((o[t][2] + p1.x) * i1, (o[t][3] + p1.y) * i1, hi, lo);
            *reinterpret_cast<uint32_t*>(&g_Ah[(size_t)(row0 + 8) * ATTN_N + col]) = hi;
            *reinterpret_cast<uint32_t*>(&g_Al[(size_t)(row0 + 8) * ATTN_N + col]) = lo;
        }
    }
}

// ---------------------------------------------------------------------------
extern "C" void kernel_launch(void* const* d_in, const int* in_sizes, int n_in,
                              void* d_out, int out_size)
{
    const float* hidden = (const float*)d_in[0];
    const float* Wqkv   = (const float*)d_in[1];
    const float* Wo     = (const float*)d_in[2];
    const float* fcos   = (const float*)d_in[3];
    const float* fsin   = (const float*)d_in[4];
    float* out = (float*)d_out;

    float* qkv_ptr;
    __nv_bfloat16 *Ah, *Al, *Bh, *Bl;
    cudaGetSymbolAddress((void**)&qkv_ptr, g_qkv);
    cudaGetSymbolAddress((void**)&Ah, g_Ah);
    cudaGetSymbolAddress((void**)&Al, g_Al);
    cudaGetSymbolAddress((void**)&Bh, g_Bh);
    cudaGetSymbolAddress((void**)&Bl, g_Bl);

    const int gemm_smem = NSTG * STAGE_B;                 // 75776
    cudaFuncSetAttribute(gemm_mma, cudaFuncAttributeMaxDynamicSharedMemorySize, gemm_smem);
    cudaFuncSetAttribute(attn_mma_kernel, cudaFuncAttributeMaxDynamicSharedMemorySize, ATTN_SMEM);

    conv_split<<<(S_LEN * HID_DIM / 4) / 256, 256>>>(
        (const float4*)hidden, (__nv_bfloat162*)Ah, (__nv_bfloat162*)Al);
    conv_split<<<((size_t)HID_DIM * QKV_N / 4) / 256, 256>>>(
        (const float4*)Wqkv, (__nv_bfloat162*)Bh, (__nv_bfloat162*)Bl);
    gemm_mma<<<dim3(QKV_N / BN, S_LEN / BM), 256, gemm_smem>>>(Ah, Al, Bh, Bl,
                                                               qkv_ptr, QKV_N, HID_DIM);

    rope_split_kernel<<<S_LEN, 256>>>(fcos, fsin);

    attn_mma_kernel<<<dim3(S_LEN / 64, NH), 256, ATTN_SMEM>>>();

    conv_split<<<((size_t)ATTN_N * HID_DIM / 4) / 256, 256>>>(
        (const float4*)Wo, (__nv_bfloat162*)Bh, (__nv_bfloat162*)Bl);
    gemm_mma<<<dim3(HID_DIM / BN, S_LEN / BM), 256, gemm_smem>>>(Ah, Al, Bh, Bl,
                                                                 out, HID_DIM, ATTN_N);
}

// round 10
// speedup vs baseline: 2.2189x; 1.1188x over previous
#include <cuda_runtime.h>
#include <cuda_bf16.h>
#include <math.h>
#include <stdint.h>

#define S_LEN   2048
#define HID_DIM 3584
#define NH      16
#define NKV     8
#define HD      256
#define QKV_N   ((NH + 2 * NKV) * HD)   // 8192
#define ATTN_N  (NH * HD)               // 4096
#define WIN     1024
#define SOFTCAP 50.0f
#define SCALING 0.0625f

// ---------------- scratch (__device__ globals; no allocs allowed) ----------
__device__ __align__(256) float g_qkv[S_LEN * QKV_N];    // 64 MB
__device__ __align__(256) __nv_bfloat16 g_Ah[S_LEN * 4096];
__device__ __align__(256) __nv_bfloat16 g_Al[S_LEN * 4096];
__device__ __align__(256) __nv_bfloat16 g_Bh[8192 * 3584];
__device__ __align__(256) __nv_bfloat16 g_Bl[8192 * 3584];
// per-head bf16 planes for attention
__device__ __align__(256) __nv_bfloat16 g_Qh[NH  * S_LEN * HD];
__device__ __align__(256) __nv_bfloat16 g_Ql[NH  * S_LEN * HD];
__device__ __align__(256) __nv_bfloat16 g_Kh[NKV * S_LEN * HD];
__device__ __align__(256) __nv_bfloat16 g_Kl[NKV * S_LEN * HD];
__device__ __align__(256) __nv_bfloat16 g_Vh[NKV * S_LEN * HD];
__device__ __align__(256) __nv_bfloat16 g_Vl[NKV * S_LEN * HD];

// ---------------- PTX helpers ----------------------------------------------
__device__ __forceinline__ uint32_t smem_u32(const void* p) {
    uint32_t a;
    asm("{ .reg .u64 t; cvta.to.shared.u64 t, %1; cvt.u32.u64 %0, t; }" : "=r"(a) : "l"(p));
    return a;
}
#define CP_ASYNC16(dst, src) \
    asm volatile("cp.async.cg.shared.global [%0], [%1], 16;" :: "r"(dst), "l"(src) : "memory")
#define CP_COMMIT() asm volatile("cp.async.commit_group;" ::: "memory")
#define CP_WAIT1()  asm volatile("cp.async.wait_group 1;" ::: "memory")

#define LDSM_X4(r0, r1, r2, r3, addr) \
    asm volatile("ldmatrix.sync.aligned.m8n8.x4.shared.b16 {%0,%1,%2,%3}, [%4];" \
        : "=r"(r0), "=r"(r1), "=r"(r2), "=r"(r3) : "r"(addr))
#define LDSM_X4T(r0, r1, r2, r3, addr) \
    asm volatile("ldmatrix.sync.aligned.m8n8.x4.trans.shared.b16 {%0,%1,%2,%3}, [%4];" \
        : "=r"(r0), "=r"(r1), "=r"(r2), "=r"(r3) : "r"(addr))

#define MMA_BF16(d, a, b0, b1) \
    asm volatile("mma.sync.aligned.m16n8k16.row.col.f32.bf16.bf16.f32 " \
        "{%0,%1,%2,%3}, {%4,%5,%6,%7}, {%8,%9}, {%0,%1,%2,%3};" \
        : "+f"((d)[0]), "+f"((d)[1]), "+f"((d)[2]), "+f"((d)[3]) \
        : "r"((a)[0]), "r"((a)[1]), "r"((a)[2]), "r"((a)[3]), "r"(b0), "r"(b1))

__device__ __forceinline__ void split_bf16(float x, __nv_bfloat16& h, __nv_bfloat16& l) {
    h = __float2bfloat16_rn(x);
    l = __float2bfloat16_rn(x - __bfloat162float(h));
}
__device__ __forceinline__ void split2(float a, float b, uint32_t& hi, uint32_t& lo) {
    __nv_bfloat16 ha, la, hb, lb;
    split_bf16(a, ha, la); split_bf16(b, hb, lb);
    __nv_bfloat162 H; H.x = ha; H.y = hb;
    __nv_bfloat162 L; L.x = la; L.y = lb;
    hi = *reinterpret_cast<uint32_t*>(&H);
    lo = *reinterpret_cast<uint32_t*>(&L);
}

// ---------------------------------------------------------------------------
// conv_split: fp32 row-major -> hi/lo bf16, same layout. 4 elems/thread.
// ---------------------------------------------------------------------------
__global__ void conv_split(const float4* __restrict__ X, __nv_bfloat162* __restrict__ H,
                           __nv_bfloat162* __restrict__ L)
{
    const size_t i = (size_t)blockIdx.x * blockDim.x + threadIdx.x;
    float4 v = X[i];
    __nv_bfloat16 h0, l0, h1, l1, h2, l2, h3, l3;
    split_bf16(v.x, h0, l0); split_bf16(v.y, h1, l1);
    split_bf16(v.z, h2, l2); split_bf16(v.w, h3, l3);
    __nv_bfloat162 a, b, c, d;
    a.x = h0; a.y = h1;  b.x = h2; b.y = h3;
    c.x = l0; c.y = l1;  d.x = l2; d.y = l3;
    H[2 * i] = a; H[2 * i + 1] = b;
    L[2 * i] = c; L[2 * i + 1] = d;
}

// ---------------------------------------------------------------------------
// HMMA split-bf16 GEMM. R4 structure; __launch_bounds__(256, 2) forces
// regs<=128 so TWO CTAs fit per SM (4 warps/SMSP instead of 2).
// ---------------------------------------------------------------------------
#define BM   128
#define BN   128
#define BK   32
#define LDA  40
#define LDB  136
#define TILE_A_B (128 * LDA * 2)
#define TILE_B_B (32 * LDB * 2)
#define OFF_AH   0
#define OFF_AL   (TILE_A_B)
#define OFF_BH   (2 * TILE_A_B)
#define OFF_BL   (2 * TILE_A_B + TILE_B_B)
#define STAGE_B  (2 * TILE_A_B + 2 * TILE_B_B)
#define NSTG 2

__global__ void __launch_bounds__(256, 2)
gemm_mma(const __nv_bfloat16* __restrict__ Ah, const __nv_bfloat16* __restrict__ Al,
         const __nv_bfloat16* __restrict__ Bh, const __nv_bfloat16* __restrict__ Bl,
         float* __restrict__ C, int N, int K)
{
    extern __shared__ char smbuf[];
    const uint32_t sb = smem_u32(smbuf);

    const int tid  = threadIdx.x;
    const int lane = tid & 31;
    const int wid  = tid >> 5;
    const int wm   = (wid & 3) * 32;
    const int wn   = (wid >> 2) * 64;
    const int nb   = blockIdx.x, mbk = blockIdx.y;
    const int m0   = mbk * BM, n0 = nb * BN;
    const int KT   = K / BK;

    const int ar = tid >> 1, ac = (tid & 1) * 16;
    const int br = tid >> 3, bc = (tid & 7) * 16;

    const __nv_bfloat16* gAh = Ah + (size_t)(m0 + ar) * K + ac;
    const __nv_bfloat16* gAl = Al + (size_t)(m0 + ar) * K + ac;
    const __nv_bfloat16* gBh = Bh + (size_t)br * N + n0 + bc;
    const __nv_bfloat16* gBl = Bl + (size_t)br * N + n0 + bc;

    auto load_stage = [&](int s, int c) {
        const uint32_t st = sb + s * STAGE_B;
        const size_t ka = (size_t)c * BK;
        const uint32_t sa = st + (ar * LDA + ac) * 2;
        CP_ASYNC16(sa + OFF_AH,      gAh + ka);
        CP_ASYNC16(sa + OFF_AH + 16, gAh + ka + 8);
        CP_ASYNC16(sa + OFF_AL,      gAl + ka);
        CP_ASYNC16(sa + OFF_AL + 16, gAl + ka + 8);
        const uint32_t sbm = st + (br * LDB + bc) * 2;
        const size_t kb = (size_t)c * BK * N;
        CP_ASYNC16(sbm + OFF_BH,      gBh + kb);
        CP_ASYNC16(sbm + OFF_BH + 16, gBh + kb + 8);
        CP_ASYNC16(sbm + OFF_BL,      gBl + kb);
        CP_ASYNC16(sbm + OFF_BL + 16, gBl + kb + 8);
    };

    load_stage(0, 0); CP_COMMIT();
    load_stage(1, 1); CP_COMMIT();

    float d[2][8][4];
    #pragma unroll
    for (int i = 0; i < 2; i++)
        #pragma unroll
        for (int j = 0; j < 8; j++)
            #pragma unroll
            for (int r = 0; r < 4; r++) d[i][j][r] = 0.f;

    const int lrow = lane & 15;
    const int lcol = (lane >> 4) * 8;

    for (int c = 0; c < KT; c++) {
        CP_WAIT1();
        __syncthreads();
        const uint32_t st = sb + (c & 1) * STAGE_B;

        #pragma unroll
        for (int ks = 0; ks < 2; ks++) {
            uint32_t ah[2][4], al[2][4];
            #pragma unroll
            for (int mb = 0; mb < 2; mb++) {
                const uint32_t aoff = st + ((wm + mb * 16 + lrow) * LDA + ks * 16 + lcol) * 2;
                LDSM_X4(ah[mb][0], ah[mb][1], ah[mb][2], ah[mb][3], aoff + OFF_AH);
                LDSM_X4(al[mb][0], al[mb][1], al[mb][2], al[mb][3], aoff + OFF_AL);
            }
            uint32_t bh[4][4], bl[4][4];
            #pragma unroll
            for (int ng = 0; ng < 4; ng++) {
                const uint32_t boff = st + ((ks * 16 + lrow) * LDB + wn + ng * 16 + lcol) * 2;
                LDSM_X4T(bh[ng][0], bh[ng][1], bh[ng][2], bh[ng][3], boff + OFF_BH);
                LDSM_X4T(bl[ng][0], bl[ng][1], bl[ng][2], bl[ng][3], boff + OFF_BL);
            }
            #pragma unroll
            for (int mb = 0; mb < 2; mb++) {
                #pragma unroll
                for (int ng = 0; ng < 4; ng++) {
                    MMA_BF16(d[mb][ng * 2 + 0], ah[mb], bh[ng][0], bh[ng][1]);
                    MMA_BF16(d[mb][ng * 2 + 1], ah[mb], bh[ng][2], bh[ng][3]);
                    MMA_BF16(d[mb][ng * 2 + 0], ah[mb], bl[ng][0], bl[ng][1]);
                    MMA_BF16(d[mb][ng * 2 + 1], ah[mb], bl[ng][2], bl[ng][3]);
                    MMA_BF16(d[mb][ng * 2 + 0], al[mb], bh[ng][0], bh[ng][1]);
                    MMA_BF16(d[mb][ng * 2 + 1], al[mb], bh[ng][2], bh[ng][3]);
                }
            }
        }
        __syncthreads();
        if (c + 2 < KT) load_stage(c & 1, c + 2);
        CP_COMMIT();
    }

    #pragma unroll
    for (int mb = 0; mb < 2; mb++) {
        const int row = m0 + wm + mb * 16 + (lane >> 2);
        #pragma unroll
        for (int nb8 = 0; nb8 < 8; nb8++) {
            const int col = n0 + wn + nb8 * 8 + (lane & 3) * 2;
            float2 v0 = make_float2(d[mb][nb8][0], d[mb][nb8][1]);
            float2 v1 = make_float2(d[mb][nb8][2], d[mb][nb8][3]);
            *reinterpret_cast<float2*>(C + (size_t)row * N + col) = v0;
            *reinterpret_cast<float2*>(C + (size_t)(row + 8) * N + col) = v1;
        }
    }
}

// ---------------------------------------------------------------------------
// rope_split: rope Q (scaled) and K, split Q/K/V into hi/lo bf16 head-planes.
// ---------------------------------------------------------------------------
__global__ void rope_split_kernel(const float* __restrict__ fcos, const float* __restrict__ fsin)
{
    const int s   = blockIdx.x;
    const int tid = threadIdx.x;
    const float* crow = fcos + (size_t)s * 128;
    const float* srow = fsin + (size_t)s * 128;
    const float* row  = g_qkv + (size_t)s * QKV_N;

    for (int p = tid; p < NH * 128; p += 256) {
        const int h = p >> 7, d = p & 127;
        const float c = crow[d], sn = srow[d];
        const float x1 = row[h * HD + d], x2 = row[h * HD + d + 128];
        const float y1 = (x1 * c - x2 * sn) * SCALING;
        const float y2 = (x1 * sn + x2 * c) * SCALING;
        const size_t o = ((size_t)h * S_LEN + s) * HD + d;
        __nv_bfloat16 hh, ll;
        split_bf16(y1, hh, ll); g_Qh[o] = hh; g_Ql[o] = ll;
        split_bf16(y2, hh, ll); g_Qh[o + 128] = hh; g_Ql[o + 128] = ll;
    }
    for (int p = tid; p < NKV * 128; p += 256) {
        const int h = p >> 7, d = p & 127;
        const float c = crow[d], sn = srow[d];
        const float x1 = row[(NH + h) * HD + d], x2 = row[(NH + h) * HD + d + 128];
        const float y1 = x1 * c - x2 * sn;
        const float y2 = x1 * sn + x2 * c;
        const size_t o = ((size_t)h * S_LEN + s) * HD + d;
        __nv_bfloat16 hh, ll;
        split_bf16(y1, hh, ll); g_Kh[o] = hh; g_Kl[o] = ll;
        split_bf16(y2, hh, ll); g_Kh[o + 128] = hh; g_Kl[o + 128] = ll;
    }
    for (int p = tid; p < NKV * HD; p += 256) {
        const int h = p >> 8, d = p & 255;
        const float v = row[(NH + NKV + h) * HD + d];
        const size_t o = ((size_t)h * S_LEN + s) * HD + d;
        __nv_bfloat16 hh, ll;
        split_bf16(v, hh, ll); g_Vh[o] = hh; g_Vl[o] = ll;
    }
}

// ---------------------------------------------------------------------------
// Tensor-core flash attention, 8 warps: warp-pair splits each 32-k chunk.
// (R9 structure, unchanged)
// ---------------------------------------------------------------------------
#define SROWB 528
#define QPLANE (64 * SROWB)
#define KVPLANE (32 * SROWB)
#define KVSTAGE (4 * KVPLANE)
#define ATTN_SMEM (2 * QPLANE + 2 * KVSTAGE + 256)

__global__ void __launch_bounds__(256, 1) attn_mma_kernel()
{
    extern __shared__ char smv[];
    const uint32_t sb = smem_u32(smv);
    const uint32_t QH = sb, QL = sb + QPLANE, ST0 = sb + 2 * QPLANE;
    float* sSum = reinterpret_cast<float*>(smv + 2 * QPLANE + 2 * KVSTAGE);

    const int tid  = threadIdx.x;
    const int lane = tid & 31;
    const int wid  = tid >> 5;
    const int wq   = wid >> 1;
    const int kg   = wid & 1;
    const int q0   = blockIdx.x * 64;
    const int h    = blockIdx.y;
    const int kvh  = h >> 1;

    const int lrow  = lane & 15;
    const int lcolb = (lane >> 4) * 16;
    const int g     = lane >> 2;
    const int t2    = (lane & 3) * 2;

    if (tid < 64) sSum[tid] = 0.f;

    const __nv_bfloat16* pQh = g_Qh + ((size_t)h * S_LEN + q0) * HD;
    const __nv_bfloat16* pQl = g_Ql + ((size_t)h * S_LEN + q0) * HD;
    const __nv_bfloat16* bKh = g_Kh + (size_t)kvh * S_LEN * HD;
    const __nv_bfloat16* bKl = g_Kl + (size_t)kvh * S_LEN * HD;
    const __nv_bfloat16* bVh = g_Vh + (size_t)kvh * S_LEN * HD;
    const __nv_bfloat16* bVl = g_Vl + (size_t)kvh * S_LEN * HD;

    for (int i = tid; i < 64 * 32; i += 256) {
        const int r = i >> 5, ch = i & 31;
        const uint32_t o = (uint32_t)r * SROWB + ch * 16;
        const size_t go = (size_t)r * HD + ch * 8;
        CP_ASYNC16(QH + o, pQh + go);
        CP_ASYNC16(QL + o, pQl + go);
    }

    auto load_kv = [&](int s, int kb) {
        const uint32_t base = ST0 + s * KVSTAGE;
        for (int i = tid; i < 32 * 32; i += 256) {
            const int r = i >> 5, ch = i & 31;
            const uint32_t o = (uint32_t)r * SROWB + ch * 16;
            const size_t go = (size_t)(kb + r) * HD + ch * 8;
            CP_ASYNC16(base + o,               bKh + go);
            CP_ASYNC16(base + KVPLANE + o,     bKl + go);
            CP_ASYNC16(base + 2 * KVPLANE + o, bVh + go);
            CP_ASYNC16(base + 3 * KVPLANE + o, bVl + go);
        }
    };

    const int klo = (q0 - (WIN - 1)) > 0 ? (q0 - (WIN - 1)) : 0;
    const int kb0 = klo & ~31;
    const int nch = (q0 + 64 - kb0) >> 5;

    load_kv(0, kb0); CP_COMMIT();
    if (nch > 1) load_kv(1, kb0 + 32);
    CP_COMMIT();

    float o[32][4];
    #pragma unroll
    for (int i = 0; i < 32; i++)
        #pragma unroll
        for (int r = 0; r < 4; r++) o[i][r] = 0.f;
    float rs0 = 0.f, rs1 = 0.f;
    const int qrow0 = q0 + wq * 16 + g;

    for (int ic = 0; ic < nch; ic++) {
        const int kb = kb0 + ic * 32;
        CP_WAIT1();
        __syncthreads();
        const uint32_t st = ST0 + (ic & 1) * KVSTAGE;

        float sf[2][4];
        #pragma unroll
        for (int t = 0; t < 2; t++)
            #pragma unroll
            for (int r = 0; r < 4; r++) sf[t][r] = 0.f;

        #pragma unroll
        for (int dc = 0; dc < 16; dc++) {
            const uint32_t qa = QH + (uint32_t)(wq * 16 + lrow) * SROWB + dc * 32 + lcolb;
            uint32_t ah[4], al[4];
            LDSM_X4(ah[0], ah[1], ah[2], ah[3], qa);
            LDSM_X4(al[0], al[1], al[2], al[3], qa + QPLANE);
            const uint32_t ka = st + (uint32_t)(kg * 16 + lrow) * SROWB + dc * 32 + lcolb;
            uint32_t bh[4], bl[4];
            LDSM_X4(bh[0], bh[1], bh[2], bh[3], ka);
            LDSM_X4(bl[0], bl[1], bl[2], bl[3], ka + KVPLANE);
            MMA_BF16(sf[0], ah, bh[0], bh[2]);
            MMA_BF16(sf[1], ah, bh[1], bh[3]);
            MMA_BF16(sf[0], ah, bl[0], bl[2]);
            MMA_BF16(sf[1], ah, bl[1], bl[3]);
            MMA_BF16(sf[0], al, bh[0], bh[2]);
            MMA_BF16(sf[1], al, bh[1], bh[3]);
        }

        uint32_t ph[2][2], pl[2][2];
        #pragma unroll
        for (int t = 0; t < 2; t++) {
            const int kcol = kb + kg * 16 + t * 8 + t2;
            float pv[4];
            #pragma unroll
            for (int r = 0; r < 4; r++) {
                const int q = qrow0 + ((r >= 2) ? 8 : 0);
                const int k = kcol + (r & 1);
                const float u = __expf(0.04f * sf[t][r]);
                const float p = __expf(__fdividef(-100.f, u + 1.f));
                pv[r] = (k <= q && (q - k) < WIN) ? p : 0.f;
            }
            rs0 += pv[0] + pv[1];
            rs1 += pv[2] + pv[3];
            split2(pv[0], pv[1], ph[t][0], pl[t][0]);
            split2(pv[2], pv[3], ph[t][1], pl[t][1]);
        }

        uint32_t pah[4] = { ph[0][0], ph[0][1], ph[1][0], ph[1][1] };
        uint32_t pal[4] = { pl[0][0], pl[0][1], pl[1][0], pl[1][1] };
        #pragma unroll
        for (int dc = 0; dc < 16; dc++) {
            const uint32_t va = st + 2 * KVPLANE +
                (uint32_t)(kg * 16 + lrow) * SROWB + dc * 32 + lcolb;
            uint32_t vh[4], vl[4];
            LDSM_X4T(vh[0], vh[1], vh[2], vh[3], va);
            LDSM_X4T(vl[0], vl[1], vl[2], vl[3], va + KVPLANE);
            MMA_BF16(o[dc * 2 + 0], pah, vh[0], vh[1]);
            MMA_BF16(o[dc * 2 + 1], pah, vh[2], vh[3]);
            MMA_BF16(o[dc * 2 + 0], pah, vl[0], vl[1]);
            MMA_BF16(o[dc * 2 + 1], pah, vl[2], vl[3]);
            MMA_BF16(o[dc * 2 + 0], pal, vh[0], vh[1]);
            MMA_BF16(o[dc * 2 + 1], pal, vh[2], vh[3]);
        }
        __syncthreads();
        if (ic + 2 < nch) load_kv(ic & 1, kb + 64);
        CP_COMMIT();
    }

    rs0 += __shfl_xor_sync(0xFFFFFFFFu, rs0, 1);
    rs0 += __shfl_xor_sync(0xFFFFFFFFu, rs0, 2);
    rs1 += __shfl_xor_sync(0xFFFFFFFFu, rs1, 1);
    rs1 += __shfl_xor_sync(0xFFFFFFFFu, rs1, 2);
    if ((lane & 3) == 0) {
        atomicAdd(&sSum[wq * 16 + g], rs0);
        atomicAdd(&sSum[wq * 16 + g + 8], rs1);
    }

    float* red = reinterpret_cast<float*>(smv + 2 * QPLANE + (nch & 1) * KVSTAGE);
    if (kg == 1) {
        #pragma unroll
        for (int t = 0; t < 32; t++) {
            const int c  = (t >> 1) * 16 + (t & 1) * 8 + t2;
            const int r0 = wq * 16 + g;
            *reinterpret_cast<float2*>(&red[(size_t)r0 * 256 + c])       = make_float2(o[t][0], o[t][1]);
            *reinterpret_cast<float2*>(&red[(size_t)(r0 + 8) * 256 + c]) = make_float2(o[t][2], o[t][3]);
        }
    }
    __syncthreads();
    if (kg == 0) {
        const float i0 = 1.0f / sSum[wq * 16 + g];
        const float i1 = 1.0f / sSum[wq * 16 + g + 8];
        const int row0 = q0 + wq * 16 + g;
        const int rl   = wq * 16 + g;
        #pragma unroll
        for (int t = 0; t < 32; t++) {
            const int c   = (t >> 1) * 16 + (t & 1) * 8 + t2;
            const int col = h * HD + c;
            float2 p0 = *reinterpret_cast<float2*>(&red[(size_t)rl * 256 + c]);
            float2 p1 = *reinterpret_cast<float2*>(&red[(size_t)(rl + 8) * 256 + c]);
            uint32_t hi, lo;
            split2((o[t][0] + p0.x) * i0, (o[t][1] + p0.y) * i0, hi, lo);
            *reinterpret_cast<uint32_t*>(&g_Ah[(size_t)row0 * ATTN_N + col]) = hi;
            *reinterpret_cast<uint32_t*>(&g_Al[(size_t)row0 * ATTN_N + col]) = lo;
            split2((o[t][2] + p1.x) * i1, (o[t][3] + p1.y) * i1, hi, lo);
            *reinterpret_cast<uint32_t*>(&g_Ah[(size_t)(row0 + 8) * ATTN_N + col]) = hi;
            *reinterpret_cast<uint32_t*>(&g_Al[(size_t)(row0 + 8) * ATTN_N + col]) = lo;
        }
    }
}

// ---------------------------------------------------------------------------
extern "C" void kernel_launch(void* const* d_in, const int* in_sizes, int n_in,
                              void* d_out, int out_size)
{
    const float* hidden = (const float*)d_in[0];
    const float* Wqkv   = (const float*)d_in[1];
    const float* Wo     = (const float*)d_in[2];
    const float* fcos   = (const float*)d_in[3];
    const float* fsin   = (const float*)d_in[4];
    float* out = (float*)d_out;

    float* qkv_ptr;
    __nv_bfloat16 *Ah, *Al, *Bh, *Bl;
    cudaGetSymbolAddress((void**)&qkv_ptr, g_qkv);
    cudaGetSymbolAddress((void**)&Ah, g_Ah);
    cudaGetSymbolAddress((void**)&Al, g_Al);
    cudaGetSymbolAddress((void**)&Bh, g_Bh);
    cudaGetSymbolAddress((void**)&Bl, g_Bl);

    const int gemm_smem = NSTG * STAGE_B;                 // 75776
    cudaFuncSetAttribute(gemm_mma, cudaFuncAttributeMaxDynamicSharedMemorySize, gemm_smem);
    cudaFuncSetAttribute(attn_mma_kernel, cudaFuncAttributeMaxDynamicSharedMemorySize, ATTN_SMEM);

    conv_split<<<(S_LEN * HID_DIM / 4) / 256, 256>>>(
        (const float4*)hidden, (__nv_bfloat162*)Ah, (__nv_bfloat162*)Al);
    conv_split<<<((size_t)HID_DIM * QKV_N / 4) / 256, 256>>>(
        (const float4*)Wqkv, (__nv_bfloat162*)Bh, (__nv_bfloat162*)Bl);
    gemm_mma<<<dim3(QKV_N / BN, S_LEN / BM), 256, gemm_smem>>>(Ah, Al, Bh, Bl,
                                                               qkv_ptr, QKV_N, HID_DIM);

    rope_split_kernel<<<S_LEN, 256>>>(fcos, fsin);

    attn_mma_kernel<<<dim3(S_LEN / 64, NH), 256, ATTN_SMEM>>>();

    conv_split<<<((size_t)ATTN_N * HID_DIM / 4) / 256, 256>>>(
        (const float4*)Wo, (__nv_bfloat162*)Bh, (__nv_bfloat162*)Bl);
    gemm_mma<<<dim3(HID_DIM / BN, S_LEN / BM), 256, gemm_smem>>>(Ah, Al, Bh, Bl,
                                                                 out, HID_DIM, ATTN_N);
}

// round 12
// speedup vs baseline: 2.2191x; 1.0001x over previous
#include <cuda_runtime.h>
#include <cuda_bf16.h>
#include <math.h>
#include <stdint.h>

#define S_LEN   2048
#define HID_DIM 3584
#define NH      16
#define NKV     8
#define HD      256
#define QKV_N   ((NH + 2 * NKV) * HD)   // 8192
#define ATTN_N  (NH * HD)               // 4096
#define WIN     1024
#define SOFTCAP 50.0f
#define SCALING 0.0625f

// ---------------- scratch (__device__ globals; no allocs allowed) ----------
__device__ __align__(256) float g_qkv[S_LEN * QKV_N];    // 64 MB
__device__ __align__(256) __nv_bfloat16 g_Ah[S_LEN * 4096];
__device__ __align__(256) __nv_bfloat16 g_Al[S_LEN * 4096];
__device__ __align__(256) __nv_bfloat16 g_Bh[8192 * 3584];
__device__ __align__(256) __nv_bfloat16 g_Bl[8192 * 3584];
// per-head bf16 planes for attention
__device__ __align__(256) __nv_bfloat16 g_Qh[NH  * S_LEN * HD];
__device__ __align__(256) __nv_bfloat16 g_Ql[NH  * S_LEN * HD];
__device__ __align__(256) __nv_bfloat16 g_Kh[NKV * S_LEN * HD];
__device__ __align__(256) __nv_bfloat16 g_Kl[NKV * S_LEN * HD];
__device__ __align__(256) __nv_bfloat16 g_Vh[NKV * S_LEN * HD];
__device__ __align__(256) __nv_bfloat16 g_Vl[NKV * S_LEN * HD];

// ---------------- PTX helpers ----------------------------------------------
__device__ __forceinline__ uint32_t smem_u32(const void* p) {
    uint32_t a;
    asm("{ .reg .u64 t; cvta.to.shared.u64 t, %1; cvt.u32.u64 %0, t; }" : "=r"(a) : "l"(p));
    return a;
}
#define CP_ASYNC16(dst, src) \
    asm volatile("cp.async.cg.shared.global [%0], [%1], 16;" :: "r"(dst), "l"(src) : "memory")
#define CP_COMMIT() asm volatile("cp.async.commit_group;" ::: "memory")
#define CP_WAIT1()  asm volatile("cp.async.wait_group 1;" ::: "memory")

#define LDSM_X4(r0, r1, r2, r3, addr) \
    asm volatile("ldmatrix.sync.aligned.m8n8.x4.shared.b16 {%0,%1,%2,%3}, [%4];" \
        : "=r"(r0), "=r"(r1), "=r"(r2), "=r"(r3) : "r"(addr))
#define LDSM_X4T(r0, r1, r2, r3, addr) \
    asm volatile("ldmatrix.sync.aligned.m8n8.x4.trans.shared.b16 {%0,%1,%2,%3}, [%4];" \
        : "=r"(r0), "=r"(r1), "=r"(r2), "=r"(r3) : "r"(addr))

#define MMA_BF16(d, a, b0, b1) \
    asm volatile("mma.sync.aligned.m16n8k16.row.col.f32.bf16.bf16.f32 " \
        "{%0,%1,%2,%3}, {%4,%5,%6,%7}, {%8,%9}, {%0,%1,%2,%3};" \
        : "+f"((d)[0]), "+f"((d)[1]), "+f"((d)[2]), "+f"((d)[3]) \
        : "r"((a)[0]), "r"((a)[1]), "r"((a)[2]), "r"((a)[3]), "r"(b0), "r"(b1))

__device__ __forceinline__ void split_bf16(float x, __nv_bfloat16& h, __nv_bfloat16& l) {
    h = __float2bfloat16_rn(x);
    l = __float2bfloat16_rn(x - __bfloat162float(h));
}
__device__ __forceinline__ void split2(float a, float b, uint32_t& hi, uint32_t& lo) {
    __nv_bfloat16 ha, la, hb, lb;
    split_bf16(a, ha, la); split_bf16(b, hb, lb);
    __nv_bfloat162 H; H.x = ha; H.y = hb;
    __nv_bfloat162 L; L.x = la; L.y = lb;
    hi = *reinterpret_cast<uint32_t*>(&H);
    lo = *reinterpret_cast<uint32_t*>(&L);
}

// ---------------------------------------------------------------------------
// conv_split: fp32 row-major -> hi/lo bf16, same layout. 4 elems/thread.
// ---------------------------------------------------------------------------
__global__ void conv_split(const float4* __restrict__ X, __nv_bfloat162* __restrict__ H,
                           __nv_bfloat162* __restrict__ L)
{
    const size_t i = (size_t)blockIdx.x * blockDim.x + threadIdx.x;
    float4 v = X[i];
    __nv_bfloat16 h0, l0, h1, l1, h2, l2, h3, l3;
    split_bf16(v.x, h0, l0); split_bf16(v.y, h1, l1);
    split_bf16(v.z, h2, l2); split_bf16(v.w, h3, l3);
    __nv_bfloat162 a, b, c, d;
    a.x = h0; a.y = h1;  b.x = h2; b.y = h3;
    c.x = l0; c.y = l1;  d.x = l2; d.y = l3;
    H[2 * i] = a; H[2 * i + 1] = b;
    L[2 * i] = c; L[2 * i + 1] = d;
}

// ---------------------------------------------------------------------------
// HMMA split-bf16 GEMM. Correct single-barrier 3-stage pipeline:
//   WAIT1 -> sync -> load(c+2) -> commit -> compute(c)
// WAIT1 guarantees chunk c complete (newest group is c+1); sync publishes it
// CTA-wide; the load targets stage (c+2)%3, last read at c-1, ordered by the
// same sync. __launch_bounds__(256,2): 2 CTAs/SM.
// ---------------------------------------------------------------------------
#define BM   128
#define BN   128
#define BK   32
#define LDA  40
#define LDB  136
#define TILE_A_B (128 * LDA * 2)
#define TILE_B_B (32 * LDB * 2)
#define OFF_AH   0
#define OFF_AL   (TILE_A_B)
#define OFF_BH   (2 * TILE_A_B)
#define OFF_BL   (2 * TILE_A_B + TILE_B_B)
#define STAGE_B  (2 * TILE_A_B + 2 * TILE_B_B)   // 37888
#define NSTG 3

__global__ void __launch_bounds__(256, 2)
gemm_mma(const __nv_bfloat16* __restrict__ Ah, const __nv_bfloat16* __restrict__ Al,
         const __nv_bfloat16* __restrict__ Bh, const __nv_bfloat16* __restrict__ Bl,
         float* __restrict__ C, int N, int K)
{
    extern __shared__ char smbuf[];
    const uint32_t sb = smem_u32(smbuf);

    const int tid  = threadIdx.x;
    const int lane = tid & 31;
    const int wid  = tid >> 5;
    const int wm   = (wid & 3) * 32;
    const int wn   = (wid >> 2) * 64;
    const int nb   = blockIdx.x, mbk = blockIdx.y;
    const int m0   = mbk * BM, n0 = nb * BN;
    const int KT   = K / BK;

    const int ar = tid >> 1, ac = (tid & 1) * 16;
    const int br = tid >> 3, bc = (tid & 7) * 16;

    const __nv_bfloat16* gAh = Ah + (size_t)(m0 + ar) * K + ac;
    const __nv_bfloat16* gAl = Al + (size_t)(m0 + ar) * K + ac;
    const __nv_bfloat16* gBh = Bh + (size_t)br * N + n0 + bc;
    const __nv_bfloat16* gBl = Bl + (size_t)br * N + n0 + bc;

    auto load_stage = [&](int s, int c) {
        const uint32_t st = sb + s * STAGE_B;
        const size_t ka = (size_t)c * BK;
        const uint32_t sa = st + (ar * LDA + ac) * 2;
        CP_ASYNC16(sa + OFF_AH,      gAh + ka);
        CP_ASYNC16(sa + OFF_AH + 16, gAh + ka + 8);
        CP_ASYNC16(sa + OFF_AL,      gAl + ka);
        CP_ASYNC16(sa + OFF_AL + 16, gAl + ka + 8);
        const uint32_t sbm = st + (br * LDB + bc) * 2;
        const size_t kb = (size_t)c * BK * N;
        CP_ASYNC16(sbm + OFF_BH,      gBh + kb);
        CP_ASYNC16(sbm + OFF_BH + 16, gBh + kb + 8);
        CP_ASYNC16(sbm + OFF_BL,      gBl + kb);
        CP_ASYNC16(sbm + OFF_BL + 16, gBl + kb + 8);
    };

    load_stage(0, 0); CP_COMMIT();
    load_stage(1, 1); CP_COMMIT();

    float d[2][8][4];
    #pragma unroll
    for (int i = 0; i < 2; i++)
        #pragma unroll
        for (int j = 0; j < 8; j++)
            #pragma unroll
            for (int r = 0; r < 4; r++) d[i][j][r] = 0.f;

    const int lrow = lane & 15;
    const int lcol = (lane >> 4) * 8;

    for (int c = 0; c < KT; c++) {
        CP_WAIT1();        // newest group = chunk c+1; chunk c complete (this thread)
        __syncthreads();   // publish chunk c CTA-wide; orders last read of stage (c+2)%3
        const int c2 = c + 2;
        if (c2 < KT) load_stage(c2 % NSTG, c2);
        CP_COMMIT();

        const uint32_t st = sb + (c % NSTG) * STAGE_B;

        #pragma unroll
        for (int ks = 0; ks < 2; ks++) {
            uint32_t ah[2][4], al[2][4];
            #pragma unroll
            for (int mb = 0; mb < 2; mb++) {
                const uint32_t aoff = st + ((wm + mb * 16 + lrow) * LDA + ks * 16 + lcol) * 2;
                LDSM_X4(ah[mb][0], ah[mb][1], ah[mb][2], ah[mb][3], aoff + OFF_AH);
                LDSM_X4(al[mb][0], al[mb][1], al[mb][2], al[mb][3], aoff + OFF_AL);
            }
            uint32_t bh[4][4], bl[4][4];
            #pragma unroll
            for (int ng = 0; ng < 4; ng++) {
                const uint32_t boff = st + ((ks * 16 + lrow) * LDB + wn + ng * 16 + lcol) * 2;
                LDSM_X4T(bh[ng][0], bh[ng][1], bh[ng][2], bh[ng][3], boff + OFF_BH);
                LDSM_X4T(bl[ng][0], bl[ng][1], bl[ng][2], bl[ng][3], boff + OFF_BL);
            }
            #pragma unroll
            for (int mb = 0; mb < 2; mb++) {
                #pragma unroll
                for (int ng = 0; ng < 4; ng++) {
                    MMA_BF16(d[mb][ng * 2 + 0], ah[mb], bh[ng][0], bh[ng][1]);
                    MMA_BF16(d[mb][ng * 2 + 1], ah[mb], bh[ng][2], bh[ng][3]);
                    MMA_BF16(d[mb][ng * 2 + 0], ah[mb], bl[ng][0], bl[ng][1]);
                    MMA_BF16(d[mb][ng * 2 + 1], ah[mb], bl[ng][2], bl[ng][3]);
                    MMA_BF16(d[mb][ng * 2 + 0], al[mb], bh[ng][0], bh[ng][1]);
                    MMA_BF16(d[mb][ng * 2 + 1], al[mb], bh[ng][2], bh[ng][3]);
                }
            }
        }
    }

    #pragma unroll
    for (int mb = 0; mb < 2; mb++) {
        const int row = m0 + wm + mb * 16 + (lane >> 2);
        #pragma unroll
        for (int nb8 = 0; nb8 < 8; nb8++) {
            const int col = n0 + wn + nb8 * 8 + (lane & 3) * 2;
            float2 v0 = make_float2(d[mb][nb8][0], d[mb][nb8][1]);
            float2 v1 = make_float2(d[mb][nb8][2], d[mb][nb8][3]);
            *reinterpret_cast<float2*>(C + (size_t)row * N + col) = v0;
            *reinterpret_cast<float2*>(C + (size_t)(row + 8) * N + col) = v1;
        }
    }
}

// ---------------------------------------------------------------------------
// rope_split: vectorized — 2 consecutive dims per thread, bf162 stores.
// ---------------------------------------------------------------------------
__global__ void rope_split_kernel(const float* __restrict__ fcos, const float* __restrict__ fsin)
{
    const int s   = blockIdx.x;
    const int tid = threadIdx.x;
    const float* crow = fcos + (size_t)s * 128;
    const float* srow = fsin + (size_t)s * 128;
    const float* row  = g_qkv + (size_t)s * QKV_N;

    for (int p = tid; p < NH * 64; p += 256) {
        const int h = p >> 6, d = (p & 63) * 2;
        float2 c  = *reinterpret_cast<const float2*>(crow + d);
        float2 sn = *reinterpret_cast<const float2*>(srow + d);
        float2 x1 = *reinterpret_cast<const float2*>(row + h * HD + d);
        float2 x2 = *reinterpret_cast<const float2*>(row + h * HD + d + 128);
        const float y1a = (x1.x * c.x - x2.x * sn.x) * SCALING;
        const float y1b = (x1.y * c.y - x2.y * sn.y) * SCALING;
        const float y2a = (x1.x * sn.x + x2.x * c.x) * SCALING;
        const float y2b = (x1.y * sn.y + x2.y * c.y) * SCALING;
        const size_t o = ((size_t)h * S_LEN + s) * HD + d;
        uint32_t hi, lo;
        split2(y1a, y1b, hi, lo);
        *reinterpret_cast<uint32_t*>(&g_Qh[o]) = hi;
        *reinterpret_cast<uint32_t*>(&g_Ql[o]) = lo;
        split2(y2a, y2b, hi, lo);
        *reinterpret_cast<uint32_t*>(&g_Qh[o + 128]) = hi;
        *reinterpret_cast<uint32_t*>(&g_Ql[o + 128]) = lo;
    }
    for (int p = tid; p < NKV * 64; p += 256) {
        const int h = p >> 6, d = (p & 63) * 2;
        float2 c  = *reinterpret_cast<const float2*>(crow + d);
        float2 sn = *reinterpret_cast<const float2*>(srow + d);
        float2 x1 = *reinterpret_cast<const float2*>(row + (NH + h) * HD + d);
        float2 x2 = *reinterpret_cast<const float2*>(row + (NH + h) * HD + d + 128);
        const float y1a = x1.x * c.x - x2.x * sn.x;
        const float y1b = x1.y * c.y - x2.y * sn.y;
        const float y2a = x1.x * sn.x + x2.x * c.x;
        const float y2b = x1.y * sn.y + x2.y * c.y;
        const size_t o = ((size_t)h * S_LEN + s) * HD + d;
        uint32_t hi, lo;
        split2(y1a, y1b, hi, lo);
        *reinterpret_cast<uint32_t*>(&g_Kh[o]) = hi;
        *reinterpret_cast<uint32_t*>(&g_Kl[o]) = lo;
        split2(y2a, y2b, hi, lo);
        *reinterpret_cast<uint32_t*>(&g_Kh[o + 128]) = hi;
        *reinterpret_cast<uint32_t*>(&g_Kl[o + 128]) = lo;
    }
    for (int p = tid; p < NKV * 128; p += 256) {
        const int h = p >> 7, d = (p & 127) * 2;
        float2 v = *reinterpret_cast<const float2*>(row + (NH + NKV + h) * HD + d);
        const size_t o = ((size_t)h * S_LEN + s) * HD + d;
        uint32_t hi, lo;
        split2(v.x, v.y, hi, lo);
        *reinterpret_cast<uint32_t*>(&g_Vh[o]) = hi;
        *reinterpret_cast<uint32_t*>(&g_Vl[o]) = lo;
    }
}

// ---------------------------------------------------------------------------
// Tensor-core flash attention, 8 warps: warp-pair splits each 32-k chunk.
// (R10 structure, unchanged — proven at 1906)
// ---------------------------------------------------------------------------
#define SROWB 528
#define QPLANE (64 * SROWB)
#define KVPLANE (32 * SROWB)
#define KVSTAGE (4 * KVPLANE)
#define ATTN_SMEM (2 * QPLANE + 2 * KVSTAGE + 256)

__global__ void __launch_bounds__(256, 1) attn_mma_kernel()
{
    extern __shared__ char smv[];
    const uint32_t sb = smem_u32(smv);
    const uint32_t QH = sb, QL = sb + QPLANE, ST0 = sb + 2 * QPLANE;
    float* sSum = reinterpret_cast<float*>(smv + 2 * QPLANE + 2 * KVSTAGE);

    const int tid  = threadIdx.x;
    const int lane = tid & 31;
    const int wid  = tid >> 5;
    const int wq   = wid >> 1;
    const int kg   = wid & 1;
    const int q0   = blockIdx.x * 64;
    const int h    = blockIdx.y;
    const int kvh  = h >> 1;

    const int lrow  = lane & 15;
    const int lcolb = (lane >> 4) * 16;
    const int g     = lane >> 2;
    const int t2    = (lane & 3) * 2;

    if (tid < 64) sSum[tid] = 0.f;

    const __nv_bfloat16* pQh = g_Qh + ((size_t)h * S_LEN + q0) * HD;
    const __nv_bfloat16* pQl = g_Ql + ((size_t)h * S_LEN + q0) * HD;
    const __nv_bfloat16* bKh = g_Kh + (size_t)kvh * S_LEN * HD;
    const __nv_bfloat16* bKl = g_Kl + (size_t)kvh * S_LEN * HD;
    const __nv_bfloat16* bVh = g_Vh + (size_t)kvh * S_LEN * HD;
    const __nv_bfloat16* bVl = g_Vl + (size_t)kvh * S_LEN * HD;

    for (int i = tid; i < 64 * 32; i += 256) {
        const int r = i >> 5, ch = i & 31;
        const uint32_t o = (uint32_t)r * SROWB + ch * 16;
        const size_t go = (size_t)r * HD + ch * 8;
        CP_ASYNC16(QH + o, pQh + go);
        CP_ASYNC16(QL + o, pQl + go);
    }

    auto load_kv = [&](int s, int kb) {
        const uint32_t base = ST0 + s * KVSTAGE;
        for (int i = tid; i < 32 * 32; i += 256) {
            const int r = i >> 5, ch = i & 31;
            const uint32_t o = (uint32_t)r * SROWB + ch * 16;
            const size_t go = (size_t)(kb + r) * HD + ch * 8;
            CP_ASYNC16(base + o,               bKh + go);
            CP_ASYNC16(base + KVPLANE + o,     bKl + go);
            CP_ASYNC16(base + 2 * KVPLANE + o, bVh + go);
            CP_ASYNC16(base + 3 * KVPLANE + o, bVl + go);
        }
    };

    const int klo = (q0 - (WIN - 1)) > 0 ? (q0 - (WIN - 1)) : 0;
    const int kb0 = klo & ~31;
    const int nch = (q0 + 64 - kb0) >> 5;

    load_kv(0, kb0); CP_COMMIT();
    if (nch > 1) load_kv(1, kb0 + 32);
    CP_COMMIT();

    float o[32][4];
    #pragma unroll
    for (int i = 0; i < 32; i++)
        #pragma unroll
        for (int r = 0; r < 4; r++) o[i][r] = 0.f;
    float rs0 = 0.f, rs1 = 0.f;
    const int qrow0 = q0 + wq * 16 + g;

    for (int ic = 0; ic < nch; ic++) {
        const int kb = kb0 + ic * 32;
        CP_WAIT1();
        __syncthreads();
        const uint32_t st = ST0 + (ic & 1) * KVSTAGE;

        float sf[2][4];
        #pragma unroll
        for (int t = 0; t < 2; t++)
            #pragma unroll
            for (int r = 0; r < 4; r++) sf[t][r] = 0.f;

        #pragma unroll
        for (int dc = 0; dc < 16; dc++) {
            const uint32_t qa = QH + (uint32_t)(wq * 16 + lrow) * SROWB + dc * 32 + lcolb;
            uint32_t ah[4], al[4];
            LDSM_X4(ah[0], ah[1], ah[2], ah[3], qa);
            LDSM_X4(al[0], al[1], al[2], al[3], qa + QPLANE);
            const uint32_t ka = st + (uint32_t)(kg * 16 + lrow) * SROWB + dc * 32 + lcolb;
            uint32_t bh[4], bl[4];
            LDSM_X4(bh[0], bh[1], bh[2], bh[3], ka);
            LDSM_X4(bl[0], bl[1], bl[2], bl[3], ka + KVPLANE);
            MMA_BF16(sf[0], ah, bh[0], bh[2]);
            MMA_BF16(sf[1], ah, bh[1], bh[3]);
            MMA_BF16(sf[0], ah, bl[0], bl[2]);
            MMA_BF16(sf[1], ah, bl[1], bl[3]);
            MMA_BF16(sf[0], al, bh[0], bh[2]);
            MMA_BF16(sf[1], al, bh[1], bh[3]);
        }

        uint32_t ph[2][2], pl[2][2];
        #pragma unroll
        for (int t = 0; t < 2; t++) {
            const int kcol = kb + kg * 16 + t * 8 + t2;
            float pv[4];
            #pragma unroll
            for (int r = 0; r < 4; r++) {
                const int q = qrow0 + ((r >= 2) ? 8 : 0);
                const int k = kcol + (r & 1);
                const float u = __expf(0.04f * sf[t][r]);
                const float p = __expf(__fdividef(-100.f, u + 1.f));
                pv[r] = (k <= q && (q - k) < WIN) ? p : 0.f;
            }
            rs0 += pv[0] + pv[1];
            rs1 += pv[2] + pv[3];
            split2(pv[0], pv[1], ph[t][0], pl[t][0]);
            split2(pv[2], pv[3], ph[t][1], pl[t][1]);
        }

        uint32_t pah[4] = { ph[0][0], ph[0][1], ph[1][0], ph[1][1] };
        uint32_t pal[4] = { pl[0][0], pl[0][1], pl[1][0], pl[1][1] };
        #pragma unroll
        for (int dc = 0; dc < 16; dc++) {
            const uint32_t va = st + 2 * KVPLANE +
                (uint32_t)(kg * 16 + lrow) * SROWB + dc * 32 + lcolb;
            uint32_t vh[4], vl[4];
            LDSM_X4T(vh[0], vh[1], vh[2], vh[3], va);
            LDSM_X4T(vl[0], vl[1], vl[2], vl[3], va + KVPLANE);
            MMA_BF16(o[dc * 2 + 0], pah, vh[0], vh[1]);
            MMA_BF16(o[dc * 2 + 1], pah, vh[2], vh[3]);
            MMA_BF16(o[dc * 2 + 0], pah, vl[0], vl[1]);
            MMA_BF16(o[dc * 2 + 1], pah, vl[2], vl[3]);
            MMA_BF16(o[dc * 2 + 0], pal, vh[0], vh[1]);
            MMA_BF16(o[dc * 2 + 1], pal, vh[2], vh[3]);
        }
        __syncthreads();
        if (ic + 2 < nch) load_kv(ic & 1, kb + 64);
        CP_COMMIT();
    }

    rs0 += __shfl_xor_sync(0xFFFFFFFFu, rs0, 1);
    rs0 += __shfl_xor_sync(0xFFFFFFFFu, rs0, 2);
    rs1 += __shfl_xor_sync(0xFFFFFFFFu, rs1, 1);
    rs1 += __shfl_xor_sync(0xFFFFFFFFu, rs1, 2);
    if ((lane & 3) == 0) {
        atomicAdd(&sSum[wq * 16 + g], rs0);
        atomicAdd(&sSum[wq * 16 + g + 8], rs1);
    }

    float* red = reinterpret_cast<float*>(smv + 2 * QPLANE + (nch & 1) * KVSTAGE);
    if (kg == 1) {
        #pragma unroll
        for (int t = 0; t < 32; t++) {
            const int c  = (t >> 1) * 16 + (t & 1) * 8 + t2;
            const int r0 = wq * 16 + g;
            *reinterpret_cast<float2*>(&red[(size_t)r0 * 256 + c])       = make_float2(o[t][0], o[t][1]);
            *reinterpret_cast<float2*>(&red[(size_t)(r0 + 8) * 256 + c]) = make_float2(o[t][2], o[t][3]);
        }
    }
    __syncthreads();
    if (kg == 0) {
        const float i0 = 1.0f / sSum[wq * 16 + g];
        const float i1 = 1.0f / sSum[wq * 16 + g + 8];
        const int row0 = q0 + wq * 16 + g;
        const int rl   = wq * 16 + g;
        #pragma unroll
        for (int t = 0; t < 32; t++) {
            const int c   = (t >> 1) * 16 + (t & 1) * 8 + t2;
            const int col = h * HD + c;
            float2 p0 = *reinterpret_cast<float2*>(&red[(size_t)rl * 256 + c]);
            float2 p1 = *reinterpret_cast<float2*>(&red[(size_t)(rl + 8) * 256 + c]);
            uint32_t hi, lo;
            split2((o[t][0] + p0.x) * i0, (o[t][1] + p0.y) * i0, hi, lo);
            *reinterpret_cast<uint32_t*>(&g_Ah[(size_t)row0 * ATTN_N + col]) = hi;
            *reinterpret_cast<uint32_t*>(&g_Al[(size_t)row0 * ATTN_N + col]) = lo;
            split2((o[t][2] + p1.x) * i1, (o[t][3] + p1.y) * i1, hi, lo);
            *reinterpret_cast<uint32_t*>(&g_Ah[(size_t)(row0 + 8) * ATTN_N + col]) = hi;
            *reinterpret_cast<uint32_t*>(&g_Al[(size_t)(row0 + 8) * ATTN_N + col]) = lo;
        }
    }
}

// ---------------------------------------------------------------------------
extern "C" void kernel_launch(void* const* d_in, const int* in_sizes, int n_in,
                              void* d_out, int out_size)
{
    const float* hidden = (const float*)d_in[0];
    const float* Wqkv   = (const float*)d_in[1];
    const float* Wo     = (const float*)d_in[2];
    const float* fcos   = (const float*)d_in[3];
    const float* fsin   = (const float*)d_in[4];
    float* out = (float*)d_out;

    float* qkv_ptr;
    __nv_bfloat16 *Ah, *Al, *Bh, *Bl;
    cudaGetSymbolAddress((void**)&qkv_ptr, g_qkv);
    cudaGetSymbolAddress((void**)&Ah, g_Ah);
    cudaGetSymbolAddress((void**)&Al, g_Al);
    cudaGetSymbolAddress((void**)&Bh, g_Bh);
    cudaGetSymbolAddress((void**)&Bl, g_Bl);

    const int gemm_smem = NSTG * STAGE_B;                 // 113664
    cudaFuncSetAttribute(gemm_mma, cudaFuncAttributeMaxDynamicSharedMemorySize, gemm_smem);
    cudaFuncSetAttribute(attn_mma_kernel, cudaFuncAttributeMaxDynamicSharedMemorySize, ATTN_SMEM);

    conv_split<<<(S_LEN * HID_DIM / 4) / 256, 256>>>(
        (const float4*)hidden, (__nv_bfloat162*)Ah, (__nv_bfloat162*)Al);
    conv_split<<<((size_t)HID_DIM * QKV_N / 4) / 256, 256>>>(
        (const float4*)Wqkv, (__nv_bfloat162*)Bh, (__nv_bfloat162*)Bl);
    gemm_mma<<<dim3(QKV_N / BN, S_LEN / BM), 256, gemm_smem>>>(Ah, Al, Bh, Bl,
                                                               qkv_ptr, QKV_N, HID_DIM);

    rope_split_kernel<<<S_LEN, 256>>>(fcos, fsin);

    attn_mma_kernel<<<dim3(S_LEN / 64, NH), 256, ATTN_SMEM>>>();

    conv_split<<<((size_t)ATTN_N * HID_DIM / 4) / 256, 256>>>(
        (const float4*)Wo, (__nv_bfloat162*)Bh, (__nv_bfloat162*)Bl);
    gemm_mma<<<dim3(HID_DIM / BN, S_LEN / BM), 256, gemm_smem>>>(Ah, Al, Bh, Bl,
                                                                 out, HID_DIM, ATTN_N);
}

// round 13
// speedup vs baseline: 2.2193x; 1.0001x over previous
#include <cuda_runtime.h>
#include <cuda_bf16.h>
#include <math.h>
#include <stdint.h>

#define S_LEN   2048
#define HID_DIM 3584
#define NH      16
#define NKV     8
#define HD      256
#define QKV_N   ((NH + 2 * NKV) * HD)   // 8192
#define ATTN_N  (NH * HD)               // 4096
#define WIN     1024
#define SOFTCAP 50.0f
#define SCALING 0.0625f

// ---------------- scratch (__device__ globals; no allocs allowed) ----------
__device__ __align__(256) __nv_bfloat16 g_Ah[S_LEN * 4096];
__device__ __align__(256) __nv_bfloat16 g_Al[S_LEN * 4096];
__device__ __align__(256) __nv_bfloat16 g_Bh[8192 * 3584];
__device__ __align__(256) __nv_bfloat16 g_Bl[8192 * 3584];
// per-head bf16 planes for attention. Q/K planes hold PERMUTED dims:
// plane dim 2j   = original dim j
// plane dim 2j+1 = original dim j+128
// (permutation identical for Q and K => dot products unchanged; V unpermuted)
__device__ __align__(256) __nv_bfloat16 g_Qh[NH  * S_LEN * HD];
__device__ __align__(256) __nv_bfloat16 g_Ql[NH  * S_LEN * HD];
__device__ __align__(256) __nv_bfloat16 g_Kh[NKV * S_LEN * HD];
__device__ __align__(256) __nv_bfloat16 g_Kl[NKV * S_LEN * HD];
__device__ __align__(256) __nv_bfloat16 g_Vh[NKV * S_LEN * HD];
__device__ __align__(256) __nv_bfloat16 g_Vl[NKV * S_LEN * HD];

// ---------------- PTX helpers ----------------------------------------------
__device__ __forceinline__ uint32_t smem_u32(const void* p) {
    uint32_t a;
    asm("{ .reg .u64 t; cvta.to.shared.u64 t, %1; cvt.u32.u64 %0, t; }" : "=r"(a) : "l"(p));
    return a;
}
#define CP_ASYNC16(dst, src) \
    asm volatile("cp.async.cg.shared.global [%0], [%1], 16;" :: "r"(dst), "l"(src) : "memory")
#define CP_COMMIT() asm volatile("cp.async.commit_group;" ::: "memory")
#define CP_WAIT1()  asm volatile("cp.async.wait_group 1;" ::: "memory")

#define LDSM_X4(r0, r1, r2, r3, addr) \
    asm volatile("ldmatrix.sync.aligned.m8n8.x4.shared.b16 {%0,%1,%2,%3}, [%4];" \
        : "=r"(r0), "=r"(r1), "=r"(r2), "=r"(r3) : "r"(addr))
#define LDSM_X4T(r0, r1, r2, r3, addr) \
    asm volatile("ldmatrix.sync.aligned.m8n8.x4.trans.shared.b16 {%0,%1,%2,%3}, [%4];" \
        : "=r"(r0), "=r"(r1), "=r"(r2), "=r"(r3) : "r"(addr))

#define MMA_BF16(d, a, b0, b1) \
    asm volatile("mma.sync.aligned.m16n8k16.row.col.f32.bf16.bf16.f32 " \
        "{%0,%1,%2,%3}, {%4,%5,%6,%7}, {%8,%9}, {%0,%1,%2,%3};" \
        : "+f"((d)[0]), "+f"((d)[1]), "+f"((d)[2]), "+f"((d)[3]) \
        : "r"((a)[0]), "r"((a)[1]), "r"((a)[2]), "r"((a)[3]), "r"(b0), "r"(b1))

__device__ __forceinline__ void split_bf16(float x, __nv_bfloat16& h, __nv_bfloat16& l) {
    h = __float2bfloat16_rn(x);
    l = __float2bfloat16_rn(x - __bfloat162float(h));
}
__device__ __forceinline__ void split2(float a, float b, uint32_t& hi, uint32_t& lo) {
    __nv_bfloat16 ha, la, hb, lb;
    split_bf16(a, ha, la); split_bf16(b, hb, lb);
    __nv_bfloat162 H; H.x = ha; H.y = hb;
    __nv_bfloat162 L; L.x = la; L.y = lb;
    hi = *reinterpret_cast<uint32_t*>(&H);
    lo = *reinterpret_cast<uint32_t*>(&L);
}

// ---------------------------------------------------------------------------
// conv_split: fp32 row-major -> hi/lo bf16, same layout. 4 elems/thread.
// (used for hidden/A and for Wo)
// ---------------------------------------------------------------------------
__global__ void conv_split(const float4* __restrict__ X, __nv_bfloat162* __restrict__ H,
                           __nv_bfloat162* __restrict__ L)
{
    const size_t i = (size_t)blockIdx.x * blockDim.x + threadIdx.x;
    float4 v = X[i];
    __nv_bfloat16 h0, l0, h1, l1, h2, l2, h3, l3;
    split_bf16(v.x, h0, l0); split_bf16(v.y, h1, l1);
    split_bf16(v.z, h2, l2); split_bf16(v.w, h3, l3);
    __nv_bfloat162 a, b, c, d;
    a.x = h0; a.y = h1;  b.x = h2; b.y = h3;
    c.x = l0; c.y = l1;  d.x = l2; d.y = l3;
    H[2 * i] = a; H[2 * i + 1] = b;
    L[2 * i] = c; L[2 * i + 1] = d;
}

// ---------------------------------------------------------------------------
// convB_qkv: Wqkv fp32 [K=3584, N=8192] -> hi/lo bf16 with rope-pair column
// permutation on Q/K head sections (heads 0..23): out col 2j   <- src dim j
//                                                  out col 2j+1 <- src dim j+128
// V sections (heads 24..31) copied unpermuted. One uint32 pair per thread.
// ---------------------------------------------------------------------------
__global__ void convB_qkv(const float* __restrict__ W)
{
    const size_t idx = (size_t)blockIdx.x * 256 + threadIdx.x;  // pair index
    const int k = (int)(idx >> 12);          // / 4096
    const int c = (int)((idx & 4095) << 1);  // even output col
    const int head = c >> 8;
    const int dn   = c & 255;
    float w1, w2;
    const float* rowp = W + (size_t)k * QKV_N;
    if (head < NH + NKV) {
        const int j = dn >> 1;
        w1 = rowp[head * 256 + j];
        w2 = rowp[head * 256 + j + 128];
    } else {
        w1 = rowp[c];
        w2 = rowp[c + 1];
    }
    uint32_t hi, lo;
    split2(w1, w2, hi, lo);
    const size_t o = (size_t)k * QKV_N + c;
    *reinterpret_cast<uint32_t*>(&g_Bh[o]) = hi;
    *reinterpret_cast<uint32_t*>(&g_Bl[o]) = lo;
}

// ---------------------------------------------------------------------------
// Fused epilogue store for the QKV GEMM: rope in-register (pairs adjacent
// thanks to permuted B), split to bf16 planes.
// ---------------------------------------------------------------------------
__device__ __forceinline__ void qkv_store(int row, int col, float x1, float x2,
                                          const float* __restrict__ fcos,
                                          const float* __restrict__ fsin)
{
    const int head = col >> 8;
    const int dn   = col & 255;
    uint32_t hi, lo;
    if (head < NH + NKV) {
        const int j = dn >> 1;
        const float cv = fcos[(size_t)row * 128 + j];
        const float sv = fsin[(size_t)row * 128 + j];
        float y1 = x1 * cv - x2 * sv;
        float y2 = x1 * sv + x2 * cv;
        if (head < NH) {
            y1 *= SCALING; y2 *= SCALING;
            split2(y1, y2, hi, lo);
            const size_t o = ((size_t)head * S_LEN + row) * HD + dn;
            *reinterpret_cast<uint32_t*>(&g_Qh[o]) = hi;
            *reinterpret_cast<uint32_t*>(&g_Ql[o]) = lo;
        } else {
            split2(y1, y2, hi, lo);
            const size_t o = ((size_t)(head - NH) * S_LEN + row) * HD + dn;
            *reinterpret_cast<uint32_t*>(&g_Kh[o]) = hi;
            *reinterpret_cast<uint32_t*>(&g_Kl[o]) = lo;
        }
    } else {
        split2(x1, x2, hi, lo);
        const size_t o = ((size_t)(head - NH - NKV) * S_LEN + row) * HD + dn;
        *reinterpret_cast<uint32_t*>(&g_Vh[o]) = hi;
        *reinterpret_cast<uint32_t*>(&g_Vl[o]) = lo;
    }
}

// ---------------------------------------------------------------------------
// HMMA split-bf16 GEMM. Single-barrier 3-stage pipeline (R12, proven):
//   WAIT1 -> sync -> load(c+2) -> commit -> compute(c)
// FUSE_ROPE: epilogue applies rope+split and writes attention planes
// (QKV GEMM); otherwise plain fp32 C store (out-proj).
// ---------------------------------------------------------------------------
#define BM   128
#define BN   128
#define BK   32
#define LDA  40
#define LDB  136
#define TILE_A_B (128 * LDA * 2)
#define TILE_B_B (32 * LDB * 2)
#define OFF_AH   0
#define OFF_AL   (TILE_A_B)
#define OFF_BH   (2 * TILE_A_B)
#define OFF_BL   (2 * TILE_A_B + TILE_B_B)
#define STAGE_B  (2 * TILE_A_B + 2 * TILE_B_B)   // 37888
#define NSTG 3

template <bool FUSE_ROPE>
__global__ void __launch_bounds__(256, 2)
gemm_mma(const __nv_bfloat16* __restrict__ Ah, const __nv_bfloat16* __restrict__ Al,
         const __nv_bfloat16* __restrict__ Bh, const __nv_bfloat16* __restrict__ Bl,
         float* __restrict__ C, int N, int K,
         const float* __restrict__ fcos, const float* __restrict__ fsin)
{
    extern __shared__ char smbuf[];
    const uint32_t sb = smem_u32(smbuf);

    const int tid  = threadIdx.x;
    const int lane = tid & 31;
    const int wid  = tid >> 5;
    const int wm   = (wid & 3) * 32;
    const int wn   = (wid >> 2) * 64;
    const int nb   = blockIdx.x, mbk = blockIdx.y;
    const int m0   = mbk * BM, n0 = nb * BN;
    const int KT   = K / BK;

    const int ar = tid >> 1, ac = (tid & 1) * 16;
    const int br = tid >> 3, bc = (tid & 7) * 16;

    const __nv_bfloat16* gAh = Ah + (size_t)(m0 + ar) * K + ac;
    const __nv_bfloat16* gAl = Al + (size_t)(m0 + ar) * K + ac;
    const __nv_bfloat16* gBh = Bh + (size_t)br * N + n0 + bc;
    const __nv_bfloat16* gBl = Bl + (size_t)br * N + n0 + bc;

    auto load_stage = [&](int s, int c) {
        const uint32_t st = sb + s * STAGE_B;
        const size_t ka = (size_t)c * BK;
        const uint32_t sa = st + (ar * LDA + ac) * 2;
        CP_ASYNC16(sa + OFF_AH,      gAh + ka);
        CP_ASYNC16(sa + OFF_AH + 16, gAh + ka + 8);
        CP_ASYNC16(sa + OFF_AL,      gAl + ka);
        CP_ASYNC16(sa + OFF_AL + 16, gAl + ka + 8);
        const uint32_t sbm = st + (br * LDB + bc) * 2;
        const size_t kb = (size_t)c * BK * N;
        CP_ASYNC16(sbm + OFF_BH,      gBh + kb);
        CP_ASYNC16(sbm + OFF_BH + 16, gBh + kb + 8);
        CP_ASYNC16(sbm + OFF_BL,      gBl + kb);
        CP_ASYNC16(sbm + OFF_BL + 16, gBl + kb + 8);
    };

    load_stage(0, 0); CP_COMMIT();
    load_stage(1, 1); CP_COMMIT();

    float d[2][8][4];
    #pragma unroll
    for (int i = 0; i < 2; i++)
        #pragma unroll
        for (int j = 0; j < 8; j++)
            #pragma unroll
            for (int r = 0; r < 4; r++) d[i][j][r] = 0.f;

    const int lrow = lane & 15;
    const int lcol = (lane >> 4) * 8;

    for (int c = 0; c < KT; c++) {
        CP_WAIT1();
        __syncthreads();
        const int c2 = c + 2;
        if (c2 < KT) load_stage(c2 % NSTG, c2);
        CP_COMMIT();

        const uint32_t st = sb + (c % NSTG) * STAGE_B;

        #pragma unroll
        for (int ks = 0; ks < 2; ks++) {
            uint32_t ah[2][4], al[2][4];
            #pragma unroll
            for (int mb = 0; mb < 2; mb++) {
                const uint32_t aoff = st + ((wm + mb * 16 + lrow) * LDA + ks * 16 + lcol) * 2;
                LDSM_X4(ah[mb][0], ah[mb][1], ah[mb][2], ah[mb][3], aoff + OFF_AH);
                LDSM_X4(al[mb][0], al[mb][1], al[mb][2], al[mb][3], aoff + OFF_AL);
            }
            uint32_t bh[4][4], bl[4][4];
            #pragma unroll
            for (int ng = 0; ng < 4; ng++) {
                const uint32_t boff = st + ((ks * 16 + lrow) * LDB + wn + ng * 16 + lcol) * 2;
                LDSM_X4T(bh[ng][0], bh[ng][1], bh[ng][2], bh[ng][3], boff + OFF_BH);
                LDSM_X4T(bl[ng][0], bl[ng][1], bl[ng][2], bl[ng][3], boff + OFF_BL);
            }
            #pragma unroll
            for (int mb = 0; mb < 2; mb++) {
                #pragma unroll
                for (int ng = 0; ng < 4; ng++) {
                    MMA_BF16(d[mb][ng * 2 + 0], ah[mb], bh[ng][0], bh[ng][1]);
                    MMA_BF16(d[mb][ng * 2 + 1], ah[mb], bh[ng][2], bh[ng][3]);
                    MMA_BF16(d[mb][ng * 2 + 0], ah[mb], bl[ng][0], bl[ng][1]);
                    MMA_BF16(d[mb][ng * 2 + 1], ah[mb], bl[ng][2], bl[ng][3]);
                    MMA_BF16(d[mb][ng * 2 + 0], al[mb], bh[ng][0], bh[ng][1]);
                    MMA_BF16(d[mb][ng * 2 + 1], al[mb], bh[ng][2], bh[ng][3]);
                }
            }
        }
    }

    #pragma unroll
    for (int mb = 0; mb < 2; mb++) {
        const int row = m0 + wm + mb * 16 + (lane >> 2);
        #pragma unroll
        for (int nb8 = 0; nb8 < 8; nb8++) {
            const int col = n0 + wn + nb8 * 8 + (lane & 3) * 2;
            if (FUSE_ROPE) {
                qkv_store(row,     col, d[mb][nb8][0], d[mb][nb8][1], fcos, fsin);
                qkv_store(row + 8, col, d[mb][nb8][2], d[mb][nb8][3], fcos, fsin);
            } else {
                float2 v0 = make_float2(d[mb][nb8][0], d[mb][nb8][1]);
                float2 v1 = make_float2(d[mb][nb8][2], d[mb][nb8][3]);
                *reinterpret_cast<float2*>(C + (size_t)row * N + col) = v0;
                *reinterpret_cast<float2*>(C + (size_t)(row + 8) * N + col) = v1;
            }
        }
    }
}

// ---------------------------------------------------------------------------
// Tensor-core flash attention, 8 warps: warp-pair splits each 32-k chunk.
// (R10/R12 structure, unchanged — proven at 1906)
// ---------------------------------------------------------------------------
#define SROWB 528
#define QPLANE (64 * SROWB)
#define KVPLANE (32 * SROWB)
#define KVSTAGE (4 * KVPLANE)
#define ATTN_SMEM (2 * QPLANE + 2 * KVSTAGE + 256)

__global__ void __launch_bounds__(256, 1) attn_mma_kernel()
{
    extern __shared__ char smv[];
    const uint32_t sb = smem_u32(smv);
    const uint32_t QH = sb, QL = sb + QPLANE, ST0 = sb + 2 * QPLANE;
    float* sSum = reinterpret_cast<float*>(smv + 2 * QPLANE + 2 * KVSTAGE);

    const int tid  = threadIdx.x;
    const int lane = tid & 31;
    const int wid  = tid >> 5;
    const int wq   = wid >> 1;
    const int kg   = wid & 1;
    const int q0   = blockIdx.x * 64;
    const int h    = blockIdx.y;
    const int kvh  = h >> 1;

    const int lrow  = lane & 15;
    const int lcolb = (lane >> 4) * 16;
    const int g     = lane >> 2;
    const int t2    = (lane & 3) * 2;

    if (tid < 64) sSum[tid] = 0.f;

    const __nv_bfloat16* pQh = g_Qh + ((size_t)h * S_LEN + q0) * HD;
    const __nv_bfloat16* pQl = g_Ql + ((size_t)h * S_LEN + q0) * HD;
    const __nv_bfloat16* bKh = g_Kh + (size_t)kvh * S_LEN * HD;
    const __nv_bfloat16* bKl = g_Kl + (size_t)kvh * S_LEN * HD;
    const __nv_bfloat16* bVh = g_Vh + (size_t)kvh * S_LEN * HD;
    const __nv_bfloat16* bVl = g_Vl + (size_t)kvh * S_LEN * HD;

    for (int i = tid; i < 64 * 32; i += 256) {
        const int r = i >> 5, ch = i & 31;
        const uint32_t o = (uint32_t)r * SROWB + ch * 16;
        const size_t go = (size_t)r * HD + ch * 8;
        CP_ASYNC16(QH + o, pQh + go);
        CP_ASYNC16(QL + o, pQl + go);
    }

    auto load_kv = [&](int s, int kb) {
        const uint32_t base = ST0 + s * KVSTAGE;
        for (int i = tid; i < 32 * 32; i += 256) {
            const int r = i >> 5, ch = i & 31;
            const uint32_t o = (uint32_t)r * SROWB + ch * 16;
            const size_t go = (size_t)(kb + r) * HD + ch * 8;
            CP_ASYNC16(base + o,               bKh + go);
            CP_ASYNC16(base + KVPLANE + o,     bKl + go);
            CP_ASYNC16(base + 2 * KVPLANE + o, bVh + go);
            CP_ASYNC16(base + 3 * KVPLANE + o, bVl + go);
        }
    };

    const int klo = (q0 - (WIN - 1)) > 0 ? (q0 - (WIN - 1)) : 0;
    const int kb0 = klo & ~31;
    const int nch = (q0 + 64 - kb0) >> 5;

    load_kv(0, kb0); CP_COMMIT();
    if (nch > 1) load_kv(1, kb0 + 32);
    CP_COMMIT();

    float o[32][4];
    #pragma unroll
    for (int i = 0; i < 32; i++)
        #pragma unroll
        for (int r = 0; r < 4; r++) o[i][r] = 0.f;
    float rs0 = 0.f, rs1 = 0.f;
    const int qrow0 = q0 + wq * 16 + g;

    for (int ic = 0; ic < nch; ic++) {
        const int kb = kb0 + ic * 32;
        CP_WAIT1();
        __syncthreads();
        const uint32_t st = ST0 + (ic & 1) * KVSTAGE;

        float sf[2][4];
        #pragma unroll
        for (int t = 0; t < 2; t++)
            #pragma unroll
            for (int r = 0; r < 4; r++) sf[t][r] = 0.f;

        #pragma unroll
        for (int dc = 0; dc < 16; dc++) {
            const uint32_t qa = QH + (uint32_t)(wq * 16 + lrow) * SROWB + dc * 32 + lcolb;
            uint32_t ah[4], al[4];
            LDSM_X4(ah[0], ah[1], ah[2], ah[3], qa);
            LDSM_X4(al[0], al[1], al[2], al[3], qa + QPLANE);
            const uint32_t ka = st + (uint32_t)(kg * 16 + lrow) * SROWB + dc * 32 + lcolb;
            uint32_t bh[4], bl[4];
            LDSM_X4(bh[0], bh[1], bh[2], bh[3], ka);
            LDSM_X4(bl[0], bl[1], bl[2], bl[3], ka + KVPLANE);
            MMA_BF16(sf[0], ah, bh[0], bh[2]);
            MMA_BF16(sf[1], ah, bh[1], bh[3]);
            MMA_BF16(sf[0], ah, bl[0], bl[2]);
            MMA_BF16(sf[1], ah, bl[1], bl[3]);
            MMA_BF16(sf[0], al, bh[0], bh[2]);
            MMA_BF16(sf[1], al, bh[1], bh[3]);
        }

        uint32_t ph[2][2], pl[2][2];
        #pragma unroll
        for (int t = 0; t < 2; t++) {
            const int kcol = kb + kg * 16 + t * 8 + t2;
            float pv[4];
            #pragma unroll
            for (int r = 0; r < 4; r++) {
                const int q = qrow0 + ((r >= 2) ? 8 : 0);
                const int k = kcol + (r & 1);
                const float u = __expf(0.04f * sf[t][r]);
                const float p = __expf(__fdividef(-100.f, u + 1.f));
                pv[r] = (k <= q && (q - k) < WIN) ? p : 0.f;
            }
            rs0 += pv[0] + pv[1];
            rs1 += pv[2] + pv[3];
            split2(pv[0], pv[1], ph[t][0], pl[t][0]);
            split2(pv[2], pv[3], ph[t][1], pl[t][1]);
        }

        uint32_t pah[4] = { ph[0][0], ph[0][1], ph[1][0], ph[1][1] };
        uint32_t pal[4] = { pl[0][0], pl[0][1], pl[1][0], pl[1][1] };
        #pragma unroll
        for (int dc = 0; dc < 16; dc++) {
            const uint32_t va = st + 2 * KVPLANE +
                (uint32_t)(kg * 16 + lrow) * SROWB + dc * 32 + lcolb;
            uint32_t vh[4], vl[4];
            LDSM_X4T(vh[0], vh[1], vh[2], vh[3], va);
            LDSM_X4T(vl[0], vl[1], vl[2], vl[3], va + KVPLANE);
            MMA_BF16(o[dc * 2 + 0], pah, vh[0], vh[1]);
            MMA_BF16(o[dc * 2 + 1], pah, vh[2], vh[3]);
            MMA_BF16(o[dc * 2 + 0], pah, vl[0], vl[1]);
            MMA_BF16(o[dc * 2 + 1], pah, vl[2], vl[3]);
            MMA_BF16(o[dc * 2 + 0], pal, vh[0], vh[1]);
            MMA_BF16(o[dc * 2 + 1], pal, vh[2], vh[3]);
        }
        __syncthreads();
        if (ic + 2 < nch) load_kv(ic & 1, kb + 64);
        CP_COMMIT();
    }

    rs0 += __shfl_xor_sync(0xFFFFFFFFu, rs0, 1);
    rs0 += __shfl_xor_sync(0xFFFFFFFFu, rs0, 2);
    rs1 += __shfl_xor_sync(0xFFFFFFFFu, rs1, 1);
    rs1 += __shfl_xor_sync(0xFFFFFFFFu, rs1, 2);
    if ((lane & 3) == 0) {
        atomicAdd(&sSum[wq * 16 + g], rs0);
        atomicAdd(&sSum[wq * 16 + g + 8], rs1);
    }

    float* red = reinterpret_cast<float*>(smv + 2 * QPLANE + (nch & 1) * KVSTAGE);
    if (kg == 1) {
        #pragma unroll
        for (int t = 0; t < 32; t++) {
            const int c  = (t >> 1) * 16 + (t & 1) * 8 + t2;
            const int r0 = wq * 16 + g;
            *reinterpret_cast<float2*>(&red[(size_t)r0 * 256 + c])       = make_float2(o[t][0], o[t][1]);
            *reinterpret_cast<float2*>(&red[(size_t)(r0 + 8) * 256 + c]) = make_float2(o[t][2], o[t][3]);
        }
    }
    __syncthreads();
    if (kg == 0) {
        const float i0 = 1.0f / sSum[wq * 16 + g];
        const float i1 = 1.0f / sSum[wq * 16 + g + 8];
        const int row0 = q0 + wq * 16 + g;
        const int rl   = wq * 16 + g;
        #pragma unroll
        for (int t = 0; t < 32; t++) {
            const int c   = (t >> 1) * 16 + (t & 1) * 8 + t2;
            const int col = h * HD + c;
            float2 p0 = *reinterpret_cast<float2*>(&red[(size_t)rl * 256 + c]);
            float2 p1 = *reinterpret_cast<float2*>(&red[(size_t)(rl + 8) * 256 + c]);
            uint32_t hi, lo;
            split2((o[t][0] + p0.x) * i0, (o[t][1] + p0.y) * i0, hi, lo);
            *reinterpret_cast<uint32_t*>(&g_Ah[(size_t)row0 * ATTN_N + col]) = hi;
            *reinterpret_cast<uint32_t*>(&g_Al[(size_t)row0 * ATTN_N + col]) = lo;
            split2((o[t][2] + p1.x) * i1, (o[t][3] + p1.y) * i1, hi, lo);
            *reinterpret_cast<uint32_t*>(&g_Ah[(size_t)(row0 + 8) * ATTN_N + col]) = hi;
            *reinterpret_cast<uint32_t*>(&g_Al[(size_t)(row0 + 8) * ATTN_N + col]) = lo;
        }
    }
}

// ---------------------------------------------------------------------------
extern "C" void kernel_launch(void* const* d_in, const int* in_sizes, int n_in,
                              void* d_out, int out_size)
{
    const float* hidden = (const float*)d_in[0];
    const float* Wqkv   = (const float*)d_in[1];
    const float* Wo     = (const float*)d_in[2];
    const float* fcos   = (const float*)d_in[3];
    const float* fsin   = (const float*)d_in[4];
    float* out = (float*)d_out;

    __nv_bfloat16 *Ah, *Al, *Bh, *Bl;
    cudaGetSymbolAddress((void**)&Ah, g_Ah);
    cudaGetSymbolAddress((void**)&Al, g_Al);
    cudaGetSymbolAddress((void**)&Bh, g_Bh);
    cudaGetSymbolAddress((void**)&Bl, g_Bl);

    const int gemm_smem = NSTG * STAGE_B;                 // 113664
    cudaFuncSetAttribute(gemm_mma<true>,  cudaFuncAttributeMaxDynamicSharedMemorySize, gemm_smem);
    cudaFuncSetAttribute(gemm_mma<false>, cudaFuncAttributeMaxDynamicSharedMemorySize, gemm_smem);
    cudaFuncSetAttribute(attn_mma_kernel, cudaFuncAttributeMaxDynamicSharedMemorySize, ATTN_SMEM);

    // --- A conversion + permuted QKV weight conversion ---
    conv_split<<<(S_LEN * HID_DIM / 4) / 256, 256>>>(
        (const float4*)hidden, (__nv_bfloat162*)Ah, (__nv_bfloat162*)Al);
    convB_qkv<<<(HID_DIM * (QKV_N / 2)) / 256, 256>>>(Wqkv);

    // --- QKV GEMM with fused rope+split epilogue (writes Q/K/V planes) ---
    gemm_mma<true><<<dim3(QKV_N / BN, S_LEN / BM), 256, gemm_smem>>>(
        Ah, Al, Bh, Bl, nullptr, QKV_N, HID_DIM, fcos, fsin);

    // --- Attention (planes in permuted dim order; dot invariant) ---
    attn_mma_kernel<<<dim3(S_LEN / 64, NH), 256, ATTN_SMEM>>>();

    // --- Output projection ---
    conv_split<<<((size_t)ATTN_N * HID_DIM / 4) / 256, 256>>>(
        (const float4*)Wo, (__nv_bfloat162*)Bh, (__nv_bfloat162*)Bl);
    gemm_mma<false><<<dim3(HID_DIM / BN, S_LEN / BM), 256, gemm_smem>>>(
        Ah, Al, Bh, Bl, out, HID_DIM, ATTN_N, nullptr, nullptr);
}